// round 12
// baseline (speedup 1.0000x reference)
#include <cuda_runtime.h>
#include <cuda_bf16.h>
#include <cstdint>
#include <math.h>

// ---------------------------------------------------------------------------
// HATBlock — Round 12: winrev fused into MLP2 (256-token tiles = 4 windows,
// smem-staged transposed stores straight to [B,C,H,W]).
// B=4, C=256, H=W=192, WS=8, NH=8, HD=32
// ---------------------------------------------------------------------------

#define BATCH 4
#define DIM   256
#define HH    192
#define WW_   192
#define NWH   24
#define NWIN  (BATCH*NWH*NWH)   // 2304
#define NTOK  (NWIN*64)         // 147456
#define NH    8
#define TOK_PER_B (HH*WW_)      // 36864

typedef unsigned long long u64;
typedef unsigned int u32;

// -------------------- scratch (device globals; no runtime alloc) -----------
__device__ float g_wins[(size_t)NTOK*256];     // wins / y (fp32)
__device__ float g_h   [(size_t)NTOK*256];     // attn-out bf16 alias
__device__ float g_big [(size_t)NTOK*512];     // qkv(768) / hidden(1024) as bf16
__device__ float g_part[1024];                 // pooled sums [B,256]
__device__ float g_gate[BATCH*256];
__device__ float g_wb  [786432/2];             // bf16 weights, transposed [N,K]

__device__ __forceinline__ float gelu_exact(float x) {
    return 0.5f * x * (1.0f + erff(x * 0.70710678118654752f));
}

__device__ __forceinline__ void cp_async16(void* smem, const void* gmem) {
    unsigned s = (unsigned)__cvta_generic_to_shared(smem);
    asm volatile("cp.async.ca.shared.global [%0], [%1], 16;" :: "r"(s), "l"(gmem));
}
__device__ __forceinline__ void cp_commit() { asm volatile("cp.async.commit_group;"); }
__device__ __forceinline__ void cp_wait1()  { asm volatile("cp.async.wait_group 1;" ::: "memory"); }
__device__ __forceinline__ void cp_wait2()  { asm volatile("cp.async.wait_group 2;" ::: "memory"); }

__device__ __forceinline__ void mma_bf16(float* c, const u32* a, const u32* b) {
    asm volatile(
        "mma.sync.aligned.m16n8k16.row.col.f32.bf16.bf16.f32 "
        "{%0,%1,%2,%3},{%4,%5,%6,%7},{%8,%9},{%0,%1,%2,%3};"
        : "+f"(c[0]), "+f"(c[1]), "+f"(c[2]), "+f"(c[3])
        : "r"(a[0]), "r"(a[1]), "r"(a[2]), "r"(a[3]), "r"(b[0]), "r"(b[1]));
}

__device__ __forceinline__ void ldsm4(u32& r0, u32& r1, u32& r2, u32& r3, u32 addr) {
    asm volatile("ldmatrix.sync.aligned.m8n8.x4.shared.b16 {%0,%1,%2,%3}, [%4];"
                 : "=r"(r0), "=r"(r1), "=r"(r2), "=r"(r3) : "r"(addr));
}

__device__ __forceinline__ u32 packbf(float a, float b) {
    __nv_bfloat162 t = __float22bfloat162_rn(make_float2(a, b));
    return *(u32*)&t;
}

// -------------------- weight prep: fp32 [K,N] -> bf16 [N,K] ----------------
__device__ __forceinline__ void wprep_body(const float* in, __nv_bfloat16* out,
                                           int K, int N, int n0, int k0) {
    __shared__ float tile[32][33];
    for (int r = threadIdx.y; r < 32; r += 8)
        tile[r][threadIdx.x] = in[(size_t)(k0 + r) * N + n0 + threadIdx.x];
    __syncthreads();
    for (int r = threadIdx.y; r < 32; r += 8)
        out[(size_t)(n0 + r) * K + k0 + threadIdx.x] = __float2bfloat16_rn(tile[threadIdx.x][r]);
}

__global__ void k_wprep(const float* __restrict__ in, __nv_bfloat16* __restrict__ out,
                        int K, int N) {
    wprep_body(in, out, K, N, blockIdx.x * 32, blockIdx.y * 32);
}

__global__ void k_wprep2(const float* __restrict__ inA, __nv_bfloat16* __restrict__ outA,
                         int KA, int NA, int nblkA,
                         const float* __restrict__ inB, __nv_bfloat16* __restrict__ outB,
                         int KB, int NB) {
    int blk = blockIdx.x;
    if (blk < nblkA) {
        int w = NA / 32;
        wprep_body(inA, outA, KA, NA, (blk % w) * 32, (blk / w) * 32);
    } else {
        blk -= nblkA;
        int w = NB / 32;
        wprep_body(inB, outB, KB, NB, (blk % w) * 32, (blk / w) * 32);
    }
}

// -------------------- window partition (+ zero pooled sums) ----------------
__global__ void k_winpart(const float* __restrict__ x, float* __restrict__ wins,
                          float* __restrict__ part) {
    int w0 = blockIdx.x * 32, hh = blockIdx.y;
    int b = blockIdx.z >> 3, c0 = (blockIdx.z & 7) * 32;
    if (blockIdx.x == 0 && blockIdx.y == 0 && blockIdx.z == 0) {
        int t = threadIdx.y * 32 + threadIdx.x;
#pragma unroll
        for (int i = 0; i < 4; i++) part[t + 256*i] = 0.f;
    }
    __shared__ float tile[32][33];
    for (int cc = threadIdx.y; cc < 32; cc += 8)
        tile[cc][threadIdx.x] =
            x[(((size_t)b*256 + c0 + cc)*HH + hh)*WW_ + w0 + threadIdx.x];
    __syncthreads();
    int hw = hh >> 3, i = hh & 7;
    for (int wi = threadIdx.y; wi < 32; wi += 8) {
        int w = w0 + wi, ww = w >> 3, j = w & 7;
        size_t t = (((size_t)b*NWH + hw)*NWH + ww)*64 + i*8 + j;
        wins[t*256 + c0 + threadIdx.x] = tile[threadIdx.x][wi];
    }
}

// ============================================================================
// GEMM 1: CTA tile 256x128, 8 warps (4 m x 2 n), warp tile 64x64, K chunk 32.
// A cached in smem bf16 (optionally fused gate+LN from fp32 gmem), 4-stage B.
// ============================================================================
#define AB_STR 264
#define B_STR  40
#define SMA_BR   135168
#define SMA_SCOL 176128
#define SMA_SMEM 176640

__global__ void __launch_bounds__(256, 1)
k_gemm_smA(const void* __restrict__ Ain, int a_bf16,
           const float* __restrict__ lng, const float* __restrict__ lnb,
           const float* __restrict__ gate,
           const __nv_bfloat16* __restrict__ Wt,
           const float* __restrict__ bias,
           const float* __restrict__ R,
           void* __restrict__ Cout, int c_bf16, int act,
           int Nfull, float* __restrict__ pool)
{
    extern __shared__ char smem[];
    __nv_bfloat16* Ab = (__nv_bfloat16*)smem;
    char*  Bring = smem + SMA_BR;
    float* scol = (float*)(smem + SMA_SCOL);
    const u32 sbase = (u32)__cvta_generic_to_shared(smem);

    const int tid = threadIdx.x, lane = tid & 31, wid = tid >> 5;
    const int g = lane >> 2, tig = lane & 3;
    const int arow = (wid & 3) * 64;
    const int bcol = (wid >> 2) * 64;
    const int m0 = blockIdx.x * 256;
    const int b  = m0 / TOK_PER_B;

    const int a_dr = (lane & 7) | (((lane >> 3) & 1) << 3);
    const int a_dk = (lane >> 4) << 3;
    const int quad = lane >> 3;
    const int b_dc = (lane & 7) + ((quad & 2) ? 8 : 0);
    const int b_dk = (quad & 1) << 3;

    if (a_bf16) {
        const __nv_bfloat16* Ag = (const __nv_bfloat16*)Ain + (size_t)m0 * 256;
#pragma unroll
        for (int i = 0; i < 32; i++) {
            int idx = tid + 256*i;
            int r = idx >> 5, c8 = idx & 31;
            cp_async16(Ab + r*AB_STR + c8*8, Ag + (size_t)r*256 + c8*8);
        }
        cp_commit();
    } else {
        const float* Ag = (const float*)Ain + (size_t)m0 * 256;
        const float* gp = gate ? (gate + b*256) : nullptr;
        float gv[8], lg[8], lb[8];
#pragma unroll
        for (int j = 0; j < 8; j++) {
            int c = lane*8 + j;
            gv[j] = gp ? gp[c] : 1.f;
            lg[j] = lng[c]; lb[j] = lnb[c];
        }
#pragma unroll 1
        for (int i = 0; i < 32; i++) {
            int r = wid*32 + i;
            const float4* rp = (const float4*)(Ag + (size_t)r * 256 + lane*8);
            float4 va = rp[0], vb = rp[1];
            float v[8] = {va.x, va.y, va.z, va.w, vb.x, vb.y, vb.z, vb.w};
            float s = 0.f, s2 = 0.f;
#pragma unroll
            for (int j = 0; j < 8; j++) {
                v[j] *= gv[j]; s += v[j]; s2 += v[j]*v[j];
            }
#pragma unroll
            for (int o = 16; o; o >>= 1) {
                s  += __shfl_xor_sync(0xffffffffu, s,  o);
                s2 += __shfl_xor_sync(0xffffffffu, s2, o);
            }
            float mean = s * (1.f/256.f);
            float var  = s2 * (1.f/256.f) - mean*mean;
            float inv  = rsqrtf(var + 1e-5f);
#pragma unroll
            for (int k = 0; k < 4; k++) {
                float n0 = (v[2*k  ]-mean)*inv*lg[2*k  ] + lb[2*k  ];
                float n1 = (v[2*k+1]-mean)*inv*lg[2*k+1] + lb[2*k+1];
                *(u32*)&Ab[r*AB_STR + lane*8 + 2*k] = packbf(n0, n1);
            }
        }
        __syncthreads();
    }

    const int NY = Nfull >> 7;
    const int KT = 8;
    const int TOT = NY * KT;

    auto fillB = [&](int c) {
        int ny2 = c >> 3, kt2 = c & 7, st = c & 3;
        __nv_bfloat16* Bs = (__nv_bfloat16*)(Bring + st*10240);
        const __nv_bfloat16* Wg = Wt + (size_t)(ny2*128) * 256 + kt2*32;
#pragma unroll
        for (int i = 0; i < 2; i++) {
            int idx = tid + 256*i;
            int row = idx >> 2, seg = idx & 3;
            cp_async16(Bs + row*B_STR + seg*8, Wg + (size_t)row*256 + seg*8);
        }
        cp_commit();
    };
    fillB(0); fillB(1); fillB(2);

    int ci = 0;
    for (int ny = 0; ny < NY; ny++) {
        float acc[4][8][4];
#pragma unroll
        for (int i = 0; i < 4; i++)
#pragma unroll
            for (int j = 0; j < 8; j++)
#pragma unroll
                for (int q = 0; q < 4; q++) acc[i][j][q] = 0.f;

        for (int kt = 0; kt < KT; kt++, ci++) {
            cp_wait2();
            __syncthreads();
            const u32 bsb = sbase + SMA_BR + (u32)(ci & 3)*10240;
#pragma unroll
            for (int ks = 0; ks < 2; ks++) {
                const int kb = kt*32 + ks*16;
                u32 af[4][4], bf[8][2];
#pragma unroll
                for (int mt = 0; mt < 4; mt++) {
                    u32 aaddr = sbase + (u32)(((arow + mt*16 + a_dr)*AB_STR + kb + a_dk) * 2);
                    ldsm4(af[mt][0], af[mt][1], af[mt][2], af[mt][3], aaddr);
                }
#pragma unroll
                for (int p = 0; p < 4; p++) {
                    u32 baddr = bsb + (u32)(((bcol + p*16 + b_dc)*B_STR + ks*16 + b_dk) * 2);
                    ldsm4(bf[2*p][0], bf[2*p][1], bf[2*p+1][0], bf[2*p+1][1], baddr);
                }
#pragma unroll
                for (int mt = 0; mt < 4; mt++)
#pragma unroll
                    for (int nt = 0; nt < 8; nt++)
                        mma_bf16(acc[mt][nt], af[mt], bf[nt]);
            }
            if (ci + 3 < TOT) fillB(ci + 3);
            else cp_commit();
        }

        const int ncol0 = ny * 128;
        if (c_bf16) {
            __nv_bfloat16* Cb = (__nv_bfloat16*)Cout;
#pragma unroll
            for (int nt = 0; nt < 8; nt++) {
                int colG = ncol0 + bcol + nt*8 + 2*tig;
                float b0 = bias[colG], b1 = bias[colG + 1];
#pragma unroll
                for (int mt = 0; mt < 4; mt++) {
                    size_t r0 = (size_t)m0 + arow + mt*16 + g;
                    size_t r1 = r0 + 8;
                    float v00 = acc[mt][nt][0] + b0, v01 = acc[mt][nt][1] + b1;
                    float v10 = acc[mt][nt][2] + b0, v11 = acc[mt][nt][3] + b1;
                    if (act) {
                        v00 = gelu_exact(v00); v01 = gelu_exact(v01);
                        v10 = gelu_exact(v10); v11 = gelu_exact(v11);
                    }
                    *(u32*)((__nv_bfloat16*)Cb + r0*Nfull + colG) = packbf(v00, v01);
                    *(u32*)((__nv_bfloat16*)Cb + r1*Nfull + colG) = packbf(v10, v11);
                }
            }
        } else {
            float* Cf = (float*)Cout;
            float psum[8][2];
#pragma unroll
            for (int nt = 0; nt < 8; nt++) { psum[nt][0] = 0.f; psum[nt][1] = 0.f; }
#pragma unroll
            for (int nt = 0; nt < 8; nt++) {
                int colG = ncol0 + bcol + nt*8 + 2*tig;
                float b0 = bias[colG], b1 = bias[colG + 1];
#pragma unroll
                for (int mt = 0; mt < 4; mt++) {
                    size_t r0 = (size_t)m0 + arow + mt*16 + g;
                    size_t r1 = r0 + 8;
                    float2 q0 = *(const float2*)(R + r0*Nfull + colG);
                    float2 q1 = *(const float2*)(R + r1*Nfull + colG);
                    float v00 = acc[mt][nt][0] + b0 + q0.x, v01 = acc[mt][nt][1] + b1 + q0.y;
                    float v10 = acc[mt][nt][2] + b0 + q1.x, v11 = acc[mt][nt][3] + b1 + q1.y;
                    *(float2*)(Cf + r0*Nfull + colG) = make_float2(v00, v01);
                    *(float2*)(Cf + r1*Nfull + colG) = make_float2(v10, v11);
                    psum[nt][0] += v00 + v10; psum[nt][1] += v01 + v11;
                }
            }
            if (pool) {
                __syncthreads();
                if (tid < 128) scol[tid] = 0.f;
                __syncthreads();
#pragma unroll
                for (int nt = 0; nt < 8; nt++) {
                    int colL = bcol + nt*8 + 2*tig;
                    atomicAdd(&scol[colL],     psum[nt][0]);
                    atomicAdd(&scol[colL + 1], psum[nt][1]);
                }
                __syncthreads();
                if (tid < 128) atomicAdd(pool + b*256 + ncol0 + tid, scol[tid]);
                __syncthreads();
            }
        }
    }
}

// ============================================================================
// GEMM 2 (MLP2) + fused window-reverse.
// CTA tile 256 tokens (= 4 whole windows) x 128 cols, 8 warps (4m x 2n).
// A bf16 streamed [M,1024], Wt bf16 [256,1024], 3-stage A+B ring, NY=2.
// Epilogue: acc+bias+R*gate -> smem staging [256][129] fp32 -> coalesced
// transposed stores straight to out[B,C,H,W] (32 contiguous w per (c,i)).
// smem: Aring 3 x 256x40 bf16 @0 (61,440); Bring 3 x 128x40 bf16 @61,440
//       (30,720); staging @92,160 (132,096).  Total 224,256 B.
// ============================================================================
#define SR_AST 20480
#define SR_BOFF 61440
#define SR_BST 10240
#define SR_STAGE 92160
#define SR_SMEM 224256
__global__ void __launch_bounds__(256, 1)
k_gemm_sA_rev(const __nv_bfloat16* __restrict__ Ain,
              const __nv_bfloat16* __restrict__ Wt,
              const float* __restrict__ bias,
              const float* __restrict__ R,
              const float* __restrict__ gate,
              float* __restrict__ out)
{
    extern __shared__ char smem[];
    const u32 sbase = (u32)__cvta_generic_to_shared(smem);
    float* sbuf = (float*)(smem + SR_STAGE);

    const int tid = threadIdx.x, lane = tid & 31, wid = tid >> 5;
    const int g = lane >> 2, tig = lane & 3;
    const int arow = (wid & 3) * 64;
    const int bcol = (wid >> 2) * 64;
    const int m0 = blockIdx.x * 256;
    const int b  = m0 / TOK_PER_B;

    // window geometry for the 4 windows in this tile
    const int win0 = m0 >> 6;                 // multiple of 4
    const int rem  = win0 - b * (NWH*NWH);
    const int hw8  = (rem / NWH) * 8;         // h base
    const int w0g  = (rem % NWH) * 8;         // w base (ww0*8), 32-wide span

    const int a_dr = (lane & 7) | (((lane >> 3) & 1) << 3);
    const int a_dk = (lane >> 4) << 3;
    const int quad = lane >> 3;
    const int b_dc = (lane & 7) + ((quad & 2) ? 8 : 0);
    const int b_dk = (quad & 1) << 3;

    const int KT = 32, NY = 2, TOT = 64;
    const __nv_bfloat16* Ag = Ain + (size_t)m0 * 1024;

    auto fillC = [&](int c) {
        int ny2 = c >> 5, kt2 = c & 31, st = c % 3;
        __nv_bfloat16* As = (__nv_bfloat16*)(smem + st*SR_AST);
        __nv_bfloat16* Bs = (__nv_bfloat16*)(smem + SR_BOFF + st*SR_BST);
        const __nv_bfloat16* Wg = Wt + (size_t)(ny2*128) * 1024 + kt2*32;
        const __nv_bfloat16* Ac = Ag + kt2*32;
#pragma unroll
        for (int i = 0; i < 4; i++) {
            int idx = tid + 256*i;                 // 0..1023
            int row = idx >> 2, seg = idx & 3;
            cp_async16(As + row*B_STR + seg*8, Ac + (size_t)row*1024 + seg*8);
        }
#pragma unroll
        for (int i = 0; i < 2; i++) {
            int idx = tid + 256*i;                 // 0..511
            int row = idx >> 2, seg = idx & 3;
            cp_async16(Bs + row*B_STR + seg*8, Wg + (size_t)row*1024 + seg*8);
        }
        cp_commit();
    };
    fillC(0); fillC(1);

    int ci = 0;
    for (int ny = 0; ny < NY; ny++) {
        float acc[4][8][4];
#pragma unroll
        for (int i = 0; i < 4; i++)
#pragma unroll
            for (int j = 0; j < 8; j++)
#pragma unroll
                for (int q = 0; q < 4; q++) acc[i][j][q] = 0.f;

        for (int kt = 0; kt < KT; kt++, ci++) {
            cp_wait1();
            __syncthreads();
            int st = ci % 3;
            const u32 asb = sbase + (u32)st*SR_AST;
            const u32 bsb = sbase + SR_BOFF + (u32)st*SR_BST;
#pragma unroll
            for (int ks = 0; ks < 2; ks++) {
                u32 af[4][4], bf[8][2];
#pragma unroll
                for (int mt = 0; mt < 4; mt++) {
                    u32 aaddr = asb + (u32)(((arow + mt*16 + a_dr)*B_STR + ks*16 + a_dk) * 2);
                    ldsm4(af[mt][0], af[mt][1], af[mt][2], af[mt][3], aaddr);
                }
#pragma unroll
                for (int p = 0; p < 4; p++) {
                    u32 baddr = bsb + (u32)(((bcol + p*16 + b_dc)*B_STR + ks*16 + b_dk) * 2);
                    ldsm4(bf[2*p][0], bf[2*p][1], bf[2*p+1][0], bf[2*p+1][1], baddr);
                }
#pragma unroll
                for (int mt = 0; mt < 4; mt++)
#pragma unroll
                    for (int nt = 0; nt < 8; nt++)
                        mma_bf16(acc[mt][nt], af[mt], bf[nt]);
            }
            if (ci + 2 < TOT) fillC(ci + 2);
            else cp_commit();
        }

        const int ncol0 = ny * 128;
        // epilogue -> staging
#pragma unroll
        for (int nt = 0; nt < 8; nt++) {
            int cl = bcol + nt*8 + 2*tig;          // local col 0..127
            int colG = ncol0 + cl;
            float b0 = bias[colG], b1 = bias[colG + 1];
            float g0 = gate[b*256 + colG], g1 = gate[b*256 + colG + 1];
#pragma unroll
            for (int mt = 0; mt < 4; mt++) {
                int r0 = arow + mt*16 + g;
                int r1 = r0 + 8;
                size_t gr0 = (size_t)m0 + r0, gr1 = (size_t)m0 + r1;
                float2 q0 = *(const float2*)(R + gr0*256 + colG);
                float2 q1 = *(const float2*)(R + gr1*256 + colG);
                sbuf[r0*129 + cl]     = acc[mt][nt][0] + b0 + q0.x*g0;
                sbuf[r0*129 + cl + 1] = acc[mt][nt][1] + b1 + q0.y*g1;
                sbuf[r1*129 + cl]     = acc[mt][nt][2] + b0 + q1.x*g0;
                sbuf[r1*129 + cl + 1] = acc[mt][nt][3] + b1 + q1.y*g1;
            }
        }
        __syncthreads();
        // staging -> out[B,C,H,W]; per (c,i): 32 contiguous w
        const int vj = lane & 7, vw = lane >> 3;   // j, window index
        for (int it = wid; it < 1024; it += 8) {
            int c = it >> 3, i = it & 7;
            float v = sbuf[(vw*64 + i*8 + vj)*129 + c];
            out[((size_t)(b*256 + ncol0 + c)*HH + hw8 + i)*WW_ + w0g + lane] = v;
        }
        __syncthreads();
    }
}

// ============================================================================
// Tensor-core window attention: one warp per (window, head).
// ============================================================================
__global__ void __launch_bounds__(128) k_attn_tc(const __nv_bfloat16* __restrict__ qkv,
                                                 const float* __restrict__ rel_bias,
                                                 __nv_bfloat16* __restrict__ o) {
    __shared__ __align__(16) __nv_bfloat16 VtAll[4][32][72];
    __shared__ float sbAll[4][226];

    const int lane = threadIdx.x & 31;
    const int wid  = threadIdx.x >> 5;
    const int g = lane >> 2, tig = lane & 3;
    const int win = blockIdx.x;
    const int h = blockIdx.y * 4 + wid;

    __nv_bfloat16 (*Vt)[72] = VtAll[wid];
    float* sb = sbAll[wid];
    const u32 vtb = (u32)__cvta_generic_to_shared(&VtAll[wid][0][0]);

    const int quad = lane >> 3;
    const int v_dc = (lane & 7) + ((quad & 2) ? 8 : 0);
    const int v_dk = (quad & 1) << 3;

    const __nv_bfloat16* qw = qkv + (size_t)win * 64 * 768 + h * 32;
    const __nv_bfloat16* kw = qw + 256;
    const __nv_bfloat16* vw = qw + 512;

    for (int r = lane; r < 225; r += 32) sb[r] = rel_bias[r*NH + h];

#pragma unroll
    for (int i = 0; i < 32; i++) {
        int idx = lane + 32*i;
        int n = idx >> 4, dp = idx & 15;
        u32 u = *(const u32*)(vw + (size_t)n*768 + 2*dp);
        __nv_bfloat162 v2 = *(__nv_bfloat162*)&u;
        Vt[2*dp  ][n] = v2.x;
        Vt[2*dp+1][n] = v2.y;
    }
    __syncwarp();

    u32 aQ[2][4][4];
#pragma unroll
    for (int ks = 0; ks < 2; ks++) {
        const int kc = 16*ks + 2*tig;
#pragma unroll
        for (int mt = 0; mt < 4; mt++) {
            const __nv_bfloat16* q0 = qw + (size_t)(mt*16 + g)*768 + kc;
            aQ[ks][mt][0] = *(const u32*)(q0);
            aQ[ks][mt][1] = *(const u32*)(q0 + 8*768);
            aQ[ks][mt][2] = *(const u32*)(q0 + 8);
            aQ[ks][mt][3] = *(const u32*)(q0 + 8*768 + 8);
        }
    }

    float O[4][4][4];
#pragma unroll
    for (int a = 0; a < 4; a++)
#pragma unroll
        for (int bq = 0; bq < 4; bq++)
#pragma unroll
            for (int c = 0; c < 4; c++) O[a][bq][c] = 0.f;
    float mrow[8], lrow[8];
#pragma unroll
    for (int r = 0; r < 8; r++) { mrow[r] = -1e30f; lrow[r] = 0.f; }

#pragma unroll 1
    for (int ck = 0; ck < 2; ck++) {
        float S[4][4][4];
#pragma unroll
        for (int a = 0; a < 4; a++)
#pragma unroll
            for (int bq = 0; bq < 4; bq++)
#pragma unroll
                for (int c = 0; c < 4; c++) S[a][bq][c] = 0.f;

#pragma unroll
        for (int ks = 0; ks < 2; ks++) {
            const int kc = 16*ks + 2*tig;
            u32 bK[4][2];
#pragma unroll
            for (int nt = 0; nt < 4; nt++) {
                const __nv_bfloat16* k0 = kw + (size_t)(ck*32 + nt*8 + g)*768 + kc;
                bK[nt][0] = *(const u32*)(k0);
                bK[nt][1] = *(const u32*)(k0 + 8);
            }
#pragma unroll
            for (int mt = 0; mt < 4; mt++)
#pragma unroll
                for (int nt = 0; nt < 4; nt++)
                    mma_bf16(S[mt][nt], aQ[ks][mt], bK[nt]);
        }

#pragma unroll
        for (int mt = 0; mt < 4; mt++)
#pragma unroll
            for (int nt = 0; nt < 4; nt++)
#pragma unroll
                for (int rr = 0; rr < 2; rr++)
#pragma unroll
                    for (int e = 0; e < 2; e++) {
                        int di = 2*mt + rr - (4*ck + nt) + 7;
                        int dj = g - (2*tig + e) + 7;
                        S[mt][nt][rr*2+e] = S[mt][nt][rr*2+e] * 0.17677669529663687f
                                          + sb[di*15 + dj];
                    }

#pragma unroll
        for (int mt = 0; mt < 4; mt++)
#pragma unroll
            for (int rr = 0; rr < 2; rr++) {
                const int r8 = mt*2 + rr;
                float mloc = -1e30f;
#pragma unroll
                for (int nt = 0; nt < 4; nt++) {
                    mloc = fmaxf(mloc, S[mt][nt][rr*2]);
                    mloc = fmaxf(mloc, S[mt][nt][rr*2+1]);
                }
                mloc = fmaxf(mloc, __shfl_xor_sync(0xffffffffu, mloc, 1));
                mloc = fmaxf(mloc, __shfl_xor_sync(0xffffffffu, mloc, 2));
                float newm = fmaxf(mrow[r8], mloc);
                float fsc = __expf(mrow[r8] - newm);
                mrow[r8] = newm;
                float rsum = 0.f;
#pragma unroll
                for (int nt = 0; nt < 4; nt++) {
                    float p0 = __expf(S[mt][nt][rr*2]   - newm);
                    float p1 = __expf(S[mt][nt][rr*2+1] - newm);
                    S[mt][nt][rr*2] = p0; S[mt][nt][rr*2+1] = p1;
                    rsum += p0 + p1;
                }
                rsum += __shfl_xor_sync(0xffffffffu, rsum, 1);
                rsum += __shfl_xor_sync(0xffffffffu, rsum, 2);
                lrow[r8] = lrow[r8]*fsc + rsum;
#pragma unroll
                for (int nt2 = 0; nt2 < 4; nt2++) {
                    O[mt][nt2][rr*2]   *= fsc;
                    O[mt][nt2][rr*2+1] *= fsc;
                }
            }

#pragma unroll
        for (int ks2 = 0; ks2 < 2; ks2++) {
            u32 bV[4][2];
#pragma unroll
            for (int p = 0; p < 2; p++) {
                u32 vaddr = vtb + (u32)(((p*16 + v_dc)*72 + ck*32 + ks2*16 + v_dk) * 2);
                ldsm4(bV[2*p][0], bV[2*p][1], bV[2*p+1][0], bV[2*p+1][1], vaddr);
            }
#pragma unroll
            for (int mt = 0; mt < 4; mt++) {
                u32 pa[4];
                pa[0] = packbf(S[mt][2*ks2  ][0], S[mt][2*ks2  ][1]);
                pa[1] = packbf(S[mt][2*ks2  ][2], S[mt][2*ks2  ][3]);
                pa[2] = packbf(S[mt][2*ks2+1][0], S[mt][2*ks2+1][1]);
                pa[3] = packbf(S[mt][2*ks2+1][2], S[mt][2*ks2+1][3]);
#pragma unroll
                for (int nt2 = 0; nt2 < 4; nt2++)
                    mma_bf16(O[mt][nt2], pa, bV[nt2]);
            }
        }
    }

    float invl[8];
#pragma unroll
    for (int r = 0; r < 8; r++) invl[r] = 1.f / lrow[r];
    __nv_bfloat16* ob = o + (size_t)win * 64 * 256 + h * 32;
#pragma unroll
    for (int mt = 0; mt < 4; mt++)
#pragma unroll
        for (int nt2 = 0; nt2 < 4; nt2++) {
            __nv_bfloat16* p0 = ob + (size_t)(mt*16 + g)*256 + nt2*8 + 2*tig;
            *(u32*)(p0)         = packbf(O[mt][nt2][0]*invl[2*mt],   O[mt][nt2][1]*invl[2*mt]);
            *(u32*)(p0 + 8*256) = packbf(O[mt][nt2][2]*invl[2*mt+1], O[mt][nt2][3]*invl[2*mt+1]);
        }
}

// -------------------- SE gate from completed pooled sums --------------------
__global__ void __launch_bounds__(256) k_pool_gate(const float* __restrict__ part,
                                                   const float* __restrict__ w1,
                                                   const float* __restrict__ b1,
                                                   const float* __restrict__ w2,
                                                   const float* __restrict__ b2,
                                                   float* __restrict__ gate) {
    int b = blockIdx.x;
    float pooled = part[b*256 + threadIdx.x] * (1.f / (float)TOK_PER_B);
    __shared__ float sp[256];
    __shared__ float hid[16];
    sp[threadIdx.x] = pooled;
    __syncthreads();
    if (threadIdx.x < 16) {
        float a = b1[threadIdx.x];
        for (int c = 0; c < 256; c++) a = fmaf(sp[c], w1[c*16 + threadIdx.x], a);
        hid[threadIdx.x] = fmaxf(a, 0.f);
    }
    __syncthreads();
    float g = b2[threadIdx.x];
#pragma unroll
    for (int j = 0; j < 16; j++) g = fmaf(hid[j], w2[j*256 + threadIdx.x], g);
    gate[b*256 + threadIdx.x] = 1.f / (1.f + __expf(-g));
}

// ---------------------------------------------------------------------------
extern "C" void kernel_launch(void* const* d_in, const int* in_sizes, int n_in,
                              void* d_out, int out_size) {
    const float* x      = (const float*)d_in[0];
    const float* n1_g   = (const float*)d_in[1];
    const float* n1_b   = (const float*)d_in[2];
    const float* qkv_w  = (const float*)d_in[3];
    const float* qkv_b  = (const float*)d_in[4];
    const float* proj_w = (const float*)d_in[5];
    const float* proj_b = (const float*)d_in[6];
    const float* rel_b  = (const float*)d_in[7];
    const float* se_w1  = (const float*)d_in[8];
    const float* se_b1  = (const float*)d_in[9];
    const float* se_w2  = (const float*)d_in[10];
    const float* se_b2  = (const float*)d_in[11];
    const float* n3_g   = (const float*)d_in[12];
    const float* n3_b   = (const float*)d_in[13];
    const float* mlp_w1 = (const float*)d_in[14];
    const float* mlp_b1 = (const float*)d_in[15];
    const float* mlp_w2 = (const float*)d_in[16];
    const float* mlp_b2 = (const float*)d_in[17];
    float* out = (float*)d_out;

    float *wins, *hbuf, *big, *part, *gate, *wb;
    cudaGetSymbolAddress((void**)&wins, g_wins);
    cudaGetSymbolAddress((void**)&hbuf, g_h);
    cudaGetSymbolAddress((void**)&big,  g_big);
    cudaGetSymbolAddress((void**)&part, g_part);
    cudaGetSymbolAddress((void**)&gate, g_gate);
    cudaGetSymbolAddress((void**)&wb,   g_wb);

    __nv_bfloat16* wbf   = (__nv_bfloat16*)wb;
    __nv_bfloat16* qkvW  = wbf;            // [768,256]
    __nv_bfloat16* projW = wbf + 196608;   // [256,256]
    __nv_bfloat16* w1W   = wbf + 262144;   // [1024,256]
    __nv_bfloat16* w2W   = wbf + 524288;   // [256,1024]
    __nv_bfloat16* bigb  = (__nv_bfloat16*)big;
    __nv_bfloat16* hb    = (__nv_bfloat16*)hbuf;

    cudaFuncSetAttribute(k_gemm_smA,    cudaFuncAttributeMaxDynamicSharedMemorySize, SMA_SMEM);
    cudaFuncSetAttribute(k_gemm_sA_rev, cudaFuncAttributeMaxDynamicSharedMemorySize, SR_SMEM);

    dim3 b328(32, 8);
    dim3 gtr(WW_/32, HH, BATCH*8);

    k_winpart<<<gtr, b328>>>(x, wins, part);
    k_wprep<<<dim3(24, 8),  b328>>>(qkv_w,  qkvW,  256, 768);
    k_wprep<<<dim3(32, 8),  b328>>>(mlp_w1, w1W,   256, 1024);
    k_wprep2<<<320, b328>>>(proj_w, projW, 256, 256, 64,
                            mlp_w2, w2W, 1024, 256);
    k_gemm_smA<<<NTOK/256, 256, SMA_SMEM>>>(wins, 0, n1_g, n1_b, nullptr,
                                            qkvW, qkv_b, nullptr,
                                            bigb, 1, 0, 768, nullptr);
    k_attn_tc<<<dim3(NWIN, 2), 128>>>(bigb, rel_b, hb);
    k_gemm_smA<<<NTOK/256, 256, SMA_SMEM>>>(hb, 1, nullptr, nullptr, nullptr,
                                            projW, proj_b, wins,
                                            wins, 0, 0, 256, part);
    k_pool_gate<<<BATCH, 256>>>(part, se_w1, se_b1, se_w2, se_b2, gate);
    k_gemm_smA<<<NTOK/256, 256, SMA_SMEM>>>(wins, 0, n3_g, n3_b, gate,
                                            w1W, mlp_b1, nullptr,
                                            bigb, 1, 1, 1024, nullptr);
    k_gemm_sA_rev<<<NTOK/256, 256, SR_SMEM>>>(bigb, w2W, mlp_b2, wins, gate, out);
}

// round 13
// speedup vs baseline: 1.0014x; 1.0014x over previous
#include <cuda_runtime.h>
#include <cuda_bf16.h>
#include <cstdint>
#include <math.h>

// ---------------------------------------------------------------------------
// HATBlock — Round 13: R12 compute path; weight preps packed into 2 launches
// so the QKV GEMM is launch #4 (= the one ncu captures).
// B=4, C=256, H=W=192, WS=8, NH=8, HD=32
// ---------------------------------------------------------------------------

#define BATCH 4
#define DIM   256
#define HH    192
#define WW_   192
#define NWH   24
#define NWIN  (BATCH*NWH*NWH)   // 2304
#define NTOK  (NWIN*64)         // 147456
#define NH    8
#define TOK_PER_B (HH*WW_)      // 36864

typedef unsigned long long u64;
typedef unsigned int u32;

// -------------------- scratch (device globals; no runtime alloc) -----------
__device__ float g_wins[(size_t)NTOK*256];     // wins / y (fp32)
__device__ float g_h   [(size_t)NTOK*256];     // attn-out bf16 alias
__device__ float g_big [(size_t)NTOK*512];     // qkv(768) / hidden(1024) as bf16
__device__ float g_part[1024];                 // pooled sums [B,256]
__device__ float g_gate[BATCH*256];
__device__ float g_wb  [786432/2];             // bf16 weights, transposed [N,K]

__device__ __forceinline__ float gelu_exact(float x) {
    return 0.5f * x * (1.0f + erff(x * 0.70710678118654752f));
}

__device__ __forceinline__ void cp_async16(void* smem, const void* gmem) {
    unsigned s = (unsigned)__cvta_generic_to_shared(smem);
    asm volatile("cp.async.ca.shared.global [%0], [%1], 16;" :: "r"(s), "l"(gmem));
}
__device__ __forceinline__ void cp_commit() { asm volatile("cp.async.commit_group;"); }
__device__ __forceinline__ void cp_wait1()  { asm volatile("cp.async.wait_group 1;" ::: "memory"); }
__device__ __forceinline__ void cp_wait2()  { asm volatile("cp.async.wait_group 2;" ::: "memory"); }

__device__ __forceinline__ void mma_bf16(float* c, const u32* a, const u32* b) {
    asm volatile(
        "mma.sync.aligned.m16n8k16.row.col.f32.bf16.bf16.f32 "
        "{%0,%1,%2,%3},{%4,%5,%6,%7},{%8,%9},{%0,%1,%2,%3};"
        : "+f"(c[0]), "+f"(c[1]), "+f"(c[2]), "+f"(c[3])
        : "r"(a[0]), "r"(a[1]), "r"(a[2]), "r"(a[3]), "r"(b[0]), "r"(b[1]));
}

__device__ __forceinline__ void ldsm4(u32& r0, u32& r1, u32& r2, u32& r3, u32 addr) {
    asm volatile("ldmatrix.sync.aligned.m8n8.x4.shared.b16 {%0,%1,%2,%3}, [%4];"
                 : "=r"(r0), "=r"(r1), "=r"(r2), "=r"(r3) : "r"(addr));
}

__device__ __forceinline__ u32 packbf(float a, float b) {
    __nv_bfloat162 t = __float22bfloat162_rn(make_float2(a, b));
    return *(u32*)&t;
}

// -------------------- weight prep: fp32 [K,N] -> bf16 [N,K] ----------------
__device__ __forceinline__ void wprep_body(const float* in, __nv_bfloat16* out,
                                           int K, int N, int n0, int k0) {
    __shared__ float tile[32][33];
    for (int r = threadIdx.y; r < 32; r += 8)
        tile[r][threadIdx.x] = in[(size_t)(k0 + r) * N + n0 + threadIdx.x];
    __syncthreads();
    for (int r = threadIdx.y; r < 32; r += 8)
        out[(size_t)(n0 + r) * K + k0 + threadIdx.x] = __float2bfloat16_rn(tile[threadIdx.x][r]);
}

__global__ void k_wprep2(const float* __restrict__ inA, __nv_bfloat16* __restrict__ outA,
                         int KA, int NA, int nblkA,
                         const float* __restrict__ inB, __nv_bfloat16* __restrict__ outB,
                         int KB, int NB) {
    int blk = blockIdx.x;
    if (blk < nblkA) {
        int w = NA / 32;
        wprep_body(inA, outA, KA, NA, (blk % w) * 32, (blk / w) * 32);
    } else {
        blk -= nblkA;
        int w = NB / 32;
        wprep_body(inB, outB, KB, NB, (blk % w) * 32, (blk / w) * 32);
    }
}

// -------------------- window partition (+ zero pooled sums) ----------------
__global__ void k_winpart(const float* __restrict__ x, float* __restrict__ wins,
                          float* __restrict__ part) {
    int w0 = blockIdx.x * 32, hh = blockIdx.y;
    int b = blockIdx.z >> 3, c0 = (blockIdx.z & 7) * 32;
    if (blockIdx.x == 0 && blockIdx.y == 0 && blockIdx.z == 0) {
        int t = threadIdx.y * 32 + threadIdx.x;
#pragma unroll
        for (int i = 0; i < 4; i++) part[t + 256*i] = 0.f;
    }
    __shared__ float tile[32][33];
    for (int cc = threadIdx.y; cc < 32; cc += 8)
        tile[cc][threadIdx.x] =
            x[(((size_t)b*256 + c0 + cc)*HH + hh)*WW_ + w0 + threadIdx.x];
    __syncthreads();
    int hw = hh >> 3, i = hh & 7;
    for (int wi = threadIdx.y; wi < 32; wi += 8) {
        int w = w0 + wi, ww = w >> 3, j = w & 7;
        size_t t = (((size_t)b*NWH + hw)*NWH + ww)*64 + i*8 + j;
        wins[t*256 + c0 + threadIdx.x] = tile[threadIdx.x][wi];
    }
}

// ============================================================================
// GEMM 1: CTA tile 256x128, 8 warps (4 m x 2 n), warp tile 64x64, K chunk 32.
// A cached in smem bf16 (optionally fused gate+LN from fp32 gmem), 4-stage B.
// ============================================================================
#define AB_STR 264
#define B_STR  40
#define SMA_BR   135168
#define SMA_SCOL 176128
#define SMA_SMEM 176640

__global__ void __launch_bounds__(256, 1)
k_gemm_smA(const void* __restrict__ Ain, int a_bf16,
           const float* __restrict__ lng, const float* __restrict__ lnb,
           const float* __restrict__ gate,
           const __nv_bfloat16* __restrict__ Wt,
           const float* __restrict__ bias,
           const float* __restrict__ R,
           void* __restrict__ Cout, int c_bf16, int act,
           int Nfull, float* __restrict__ pool)
{
    extern __shared__ char smem[];
    __nv_bfloat16* Ab = (__nv_bfloat16*)smem;
    char*  Bring = smem + SMA_BR;
    float* scol = (float*)(smem + SMA_SCOL);
    const u32 sbase = (u32)__cvta_generic_to_shared(smem);

    const int tid = threadIdx.x, lane = tid & 31, wid = tid >> 5;
    const int g = lane >> 2, tig = lane & 3;
    const int arow = (wid & 3) * 64;
    const int bcol = (wid >> 2) * 64;
    const int m0 = blockIdx.x * 256;
    const int b  = m0 / TOK_PER_B;

    const int a_dr = (lane & 7) | (((lane >> 3) & 1) << 3);
    const int a_dk = (lane >> 4) << 3;
    const int quad = lane >> 3;
    const int b_dc = (lane & 7) + ((quad & 2) ? 8 : 0);
    const int b_dk = (quad & 1) << 3;

    if (a_bf16) {
        const __nv_bfloat16* Ag = (const __nv_bfloat16*)Ain + (size_t)m0 * 256;
#pragma unroll
        for (int i = 0; i < 32; i++) {
            int idx = tid + 256*i;
            int r = idx >> 5, c8 = idx & 31;
            cp_async16(Ab + r*AB_STR + c8*8, Ag + (size_t)r*256 + c8*8);
        }
        cp_commit();
    } else {
        const float* Ag = (const float*)Ain + (size_t)m0 * 256;
        const float* gp = gate ? (gate + b*256) : nullptr;
        float gv[8], lg[8], lb[8];
#pragma unroll
        for (int j = 0; j < 8; j++) {
            int c = lane*8 + j;
            gv[j] = gp ? gp[c] : 1.f;
            lg[j] = lng[c]; lb[j] = lnb[c];
        }
#pragma unroll 1
        for (int i = 0; i < 32; i++) {
            int r = wid*32 + i;
            const float4* rp = (const float4*)(Ag + (size_t)r * 256 + lane*8);
            float4 va = rp[0], vb = rp[1];
            float v[8] = {va.x, va.y, va.z, va.w, vb.x, vb.y, vb.z, vb.w};
            float s = 0.f, s2 = 0.f;
#pragma unroll
            for (int j = 0; j < 8; j++) {
                v[j] *= gv[j]; s += v[j]; s2 += v[j]*v[j];
            }
#pragma unroll
            for (int o = 16; o; o >>= 1) {
                s  += __shfl_xor_sync(0xffffffffu, s,  o);
                s2 += __shfl_xor_sync(0xffffffffu, s2, o);
            }
            float mean = s * (1.f/256.f);
            float var  = s2 * (1.f/256.f) - mean*mean;
            float inv  = rsqrtf(var + 1e-5f);
#pragma unroll
            for (int k = 0; k < 4; k++) {
                float n0 = (v[2*k  ]-mean)*inv*lg[2*k  ] + lb[2*k  ];
                float n1 = (v[2*k+1]-mean)*inv*lg[2*k+1] + lb[2*k+1];
                *(u32*)&Ab[r*AB_STR + lane*8 + 2*k] = packbf(n0, n1);
            }
        }
        __syncthreads();
    }

    const int NY = Nfull >> 7;
    const int KT = 8;
    const int TOT = NY * KT;

    auto fillB = [&](int c) {
        int ny2 = c >> 3, kt2 = c & 7, st = c & 3;
        __nv_bfloat16* Bs = (__nv_bfloat16*)(Bring + st*10240);
        const __nv_bfloat16* Wg = Wt + (size_t)(ny2*128) * 256 + kt2*32;
#pragma unroll
        for (int i = 0; i < 2; i++) {
            int idx = tid + 256*i;
            int row = idx >> 2, seg = idx & 3;
            cp_async16(Bs + row*B_STR + seg*8, Wg + (size_t)row*256 + seg*8);
        }
        cp_commit();
    };
    fillB(0); fillB(1); fillB(2);

    int ci = 0;
    for (int ny = 0; ny < NY; ny++) {
        float acc[4][8][4];
#pragma unroll
        for (int i = 0; i < 4; i++)
#pragma unroll
            for (int j = 0; j < 8; j++)
#pragma unroll
                for (int q = 0; q < 4; q++) acc[i][j][q] = 0.f;

        for (int kt = 0; kt < KT; kt++, ci++) {
            cp_wait2();
            __syncthreads();
            const u32 bsb = sbase + SMA_BR + (u32)(ci & 3)*10240;
#pragma unroll
            for (int ks = 0; ks < 2; ks++) {
                const int kb = kt*32 + ks*16;
                u32 af[4][4], bf[8][2];
#pragma unroll
                for (int mt = 0; mt < 4; mt++) {
                    u32 aaddr = sbase + (u32)(((arow + mt*16 + a_dr)*AB_STR + kb + a_dk) * 2);
                    ldsm4(af[mt][0], af[mt][1], af[mt][2], af[mt][3], aaddr);
                }
#pragma unroll
                for (int p = 0; p < 4; p++) {
                    u32 baddr = bsb + (u32)(((bcol + p*16 + b_dc)*B_STR + ks*16 + b_dk) * 2);
                    ldsm4(bf[2*p][0], bf[2*p][1], bf[2*p+1][0], bf[2*p+1][1], baddr);
                }
#pragma unroll
                for (int mt = 0; mt < 4; mt++)
#pragma unroll
                    for (int nt = 0; nt < 8; nt++)
                        mma_bf16(acc[mt][nt], af[mt], bf[nt]);
            }
            if (ci + 3 < TOT) fillB(ci + 3);
            else cp_commit();
        }

        const int ncol0 = ny * 128;
        if (c_bf16) {
            __nv_bfloat16* Cb = (__nv_bfloat16*)Cout;
#pragma unroll
            for (int nt = 0; nt < 8; nt++) {
                int colG = ncol0 + bcol + nt*8 + 2*tig;
                float b0 = bias[colG], b1 = bias[colG + 1];
#pragma unroll
                for (int mt = 0; mt < 4; mt++) {
                    size_t r0 = (size_t)m0 + arow + mt*16 + g;
                    size_t r1 = r0 + 8;
                    float v00 = acc[mt][nt][0] + b0, v01 = acc[mt][nt][1] + b1;
                    float v10 = acc[mt][nt][2] + b0, v11 = acc[mt][nt][3] + b1;
                    if (act) {
                        v00 = gelu_exact(v00); v01 = gelu_exact(v01);
                        v10 = gelu_exact(v10); v11 = gelu_exact(v11);
                    }
                    *(u32*)((__nv_bfloat16*)Cb + r0*Nfull + colG) = packbf(v00, v01);
                    *(u32*)((__nv_bfloat16*)Cb + r1*Nfull + colG) = packbf(v10, v11);
                }
            }
        } else {
            float* Cf = (float*)Cout;
            float psum[8][2];
#pragma unroll
            for (int nt = 0; nt < 8; nt++) { psum[nt][0] = 0.f; psum[nt][1] = 0.f; }
#pragma unroll
            for (int nt = 0; nt < 8; nt++) {
                int colG = ncol0 + bcol + nt*8 + 2*tig;
                float b0 = bias[colG], b1 = bias[colG + 1];
#pragma unroll
                for (int mt = 0; mt < 4; mt++) {
                    size_t r0 = (size_t)m0 + arow + mt*16 + g;
                    size_t r1 = r0 + 8;
                    float2 q0 = *(const float2*)(R + r0*Nfull + colG);
                    float2 q1 = *(const float2*)(R + r1*Nfull + colG);
                    float v00 = acc[mt][nt][0] + b0 + q0.x, v01 = acc[mt][nt][1] + b1 + q0.y;
                    float v10 = acc[mt][nt][2] + b0 + q1.x, v11 = acc[mt][nt][3] + b1 + q1.y;
                    *(float2*)(Cf + r0*Nfull + colG) = make_float2(v00, v01);
                    *(float2*)(Cf + r1*Nfull + colG) = make_float2(v10, v11);
                    psum[nt][0] += v00 + v10; psum[nt][1] += v01 + v11;
                }
            }
            if (pool) {
                __syncthreads();
                if (tid < 128) scol[tid] = 0.f;
                __syncthreads();
#pragma unroll
                for (int nt = 0; nt < 8; nt++) {
                    int colL = bcol + nt*8 + 2*tig;
                    atomicAdd(&scol[colL],     psum[nt][0]);
                    atomicAdd(&scol[colL + 1], psum[nt][1]);
                }
                __syncthreads();
                if (tid < 128) atomicAdd(pool + b*256 + ncol0 + tid, scol[tid]);
                __syncthreads();
            }
        }
    }
}

// ============================================================================
// GEMM 2 (MLP2) + fused window-reverse (256 tokens = 4 windows per CTA).
// ============================================================================
#define SR_AST 20480
#define SR_BOFF 61440
#define SR_BST 10240
#define SR_STAGE 92160
#define SR_SMEM 224256
__global__ void __launch_bounds__(256, 1)
k_gemm_sA_rev(const __nv_bfloat16* __restrict__ Ain,
              const __nv_bfloat16* __restrict__ Wt,
              const float* __restrict__ bias,
              const float* __restrict__ R,
              const float* __restrict__ gate,
              float* __restrict__ out)
{
    extern __shared__ char smem[];
    const u32 sbase = (u32)__cvta_generic_to_shared(smem);
    float* sbuf = (float*)(smem + SR_STAGE);

    const int tid = threadIdx.x, lane = tid & 31, wid = tid >> 5;
    const int g = lane >> 2, tig = lane & 3;
    const int arow = (wid & 3) * 64;
    const int bcol = (wid >> 2) * 64;
    const int m0 = blockIdx.x * 256;
    const int b  = m0 / TOK_PER_B;

    const int win0 = m0 >> 6;
    const int rem  = win0 - b * (NWH*NWH);
    const int hw8  = (rem / NWH) * 8;
    const int w0g  = (rem % NWH) * 8;

    const int a_dr = (lane & 7) | (((lane >> 3) & 1) << 3);
    const int a_dk = (lane >> 4) << 3;
    const int quad = lane >> 3;
    const int b_dc = (lane & 7) + ((quad & 2) ? 8 : 0);
    const int b_dk = (quad & 1) << 3;

    const int KT = 32, NY = 2, TOT = 64;
    const __nv_bfloat16* Ag = Ain + (size_t)m0 * 1024;

    auto fillC = [&](int c) {
        int ny2 = c >> 5, kt2 = c & 31, st = c % 3;
        __nv_bfloat16* As = (__nv_bfloat16*)(smem + st*SR_AST);
        __nv_bfloat16* Bs = (__nv_bfloat16*)(smem + SR_BOFF + st*SR_BST);
        const __nv_bfloat16* Wg = Wt + (size_t)(ny2*128) * 1024 + kt2*32;
        const __nv_bfloat16* Ac = Ag + kt2*32;
#pragma unroll
        for (int i = 0; i < 4; i++) {
            int idx = tid + 256*i;
            int row = idx >> 2, seg = idx & 3;
            cp_async16(As + row*B_STR + seg*8, Ac + (size_t)row*1024 + seg*8);
        }
#pragma unroll
        for (int i = 0; i < 2; i++) {
            int idx = tid + 256*i;
            int row = idx >> 2, seg = idx & 3;
            cp_async16(Bs + row*B_STR + seg*8, Wg + (size_t)row*1024 + seg*8);
        }
        cp_commit();
    };
    fillC(0); fillC(1);

    int ci = 0;
    for (int ny = 0; ny < NY; ny++) {
        float acc[4][8][4];
#pragma unroll
        for (int i = 0; i < 4; i++)
#pragma unroll
            for (int j = 0; j < 8; j++)
#pragma unroll
                for (int q = 0; q < 4; q++) acc[i][j][q] = 0.f;

        for (int kt = 0; kt < KT; kt++, ci++) {
            cp_wait1();
            __syncthreads();
            int st = ci % 3;
            const u32 asb = sbase + (u32)st*SR_AST;
            const u32 bsb = sbase + SR_BOFF + (u32)st*SR_BST;
#pragma unroll
            for (int ks = 0; ks < 2; ks++) {
                u32 af[4][4], bf[8][2];
#pragma unroll
                for (int mt = 0; mt < 4; mt++) {
                    u32 aaddr = asb + (u32)(((arow + mt*16 + a_dr)*B_STR + ks*16 + a_dk) * 2);
                    ldsm4(af[mt][0], af[mt][1], af[mt][2], af[mt][3], aaddr);
                }
#pragma unroll
                for (int p = 0; p < 4; p++) {
                    u32 baddr = bsb + (u32)(((bcol + p*16 + b_dc)*B_STR + ks*16 + b_dk) * 2);
                    ldsm4(bf[2*p][0], bf[2*p][1], bf[2*p+1][0], bf[2*p+1][1], baddr);
                }
#pragma unroll
                for (int mt = 0; mt < 4; mt++)
#pragma unroll
                    for (int nt = 0; nt < 8; nt++)
                        mma_bf16(acc[mt][nt], af[mt], bf[nt]);
            }
            if (ci + 2 < TOT) fillC(ci + 2);
            else cp_commit();
        }

        const int ncol0 = ny * 128;
#pragma unroll
        for (int nt = 0; nt < 8; nt++) {
            int cl = bcol + nt*8 + 2*tig;
            int colG = ncol0 + cl;
            float b0 = bias[colG], b1 = bias[colG + 1];
            float g0 = gate[b*256 + colG], g1 = gate[b*256 + colG + 1];
#pragma unroll
            for (int mt = 0; mt < 4; mt++) {
                int r0 = arow + mt*16 + g;
                int r1 = r0 + 8;
                size_t gr0 = (size_t)m0 + r0, gr1 = (size_t)m0 + r1;
                float2 q0 = *(const float2*)(R + gr0*256 + colG);
                float2 q1 = *(const float2*)(R + gr1*256 + colG);
                sbuf[r0*129 + cl]     = acc[mt][nt][0] + b0 + q0.x*g0;
                sbuf[r0*129 + cl + 1] = acc[mt][nt][1] + b1 + q0.y*g1;
                sbuf[r1*129 + cl]     = acc[mt][nt][2] + b0 + q1.x*g0;
                sbuf[r1*129 + cl + 1] = acc[mt][nt][3] + b1 + q1.y*g1;
            }
        }
        __syncthreads();
        const int vj = lane & 7, vw = lane >> 3;
        for (int it = wid; it < 1024; it += 8) {
            int c = it >> 3, i = it & 7;
            float v = sbuf[(vw*64 + i*8 + vj)*129 + c];
            out[((size_t)(b*256 + ncol0 + c)*HH + hw8 + i)*WW_ + w0g + lane] = v;
        }
        __syncthreads();
    }
}

// ============================================================================
// Tensor-core window attention: one warp per (window, head).
// ============================================================================
__global__ void __launch_bounds__(128) k_attn_tc(const __nv_bfloat16* __restrict__ qkv,
                                                 const float* __restrict__ rel_bias,
                                                 __nv_bfloat16* __restrict__ o) {
    __shared__ __align__(16) __nv_bfloat16 VtAll[4][32][72];
    __shared__ float sbAll[4][226];

    const int lane = threadIdx.x & 31;
    const int wid  = threadIdx.x >> 5;
    const int g = lane >> 2, tig = lane & 3;
    const int win = blockIdx.x;
    const int h = blockIdx.y * 4 + wid;

    __nv_bfloat16 (*Vt)[72] = VtAll[wid];
    float* sb = sbAll[wid];
    const u32 vtb = (u32)__cvta_generic_to_shared(&VtAll[wid][0][0]);

    const int quad = lane >> 3;
    const int v_dc = (lane & 7) + ((quad & 2) ? 8 : 0);
    const int v_dk = (quad & 1) << 3;

    const __nv_bfloat16* qw = qkv + (size_t)win * 64 * 768 + h * 32;
    const __nv_bfloat16* kw = qw + 256;
    const __nv_bfloat16* vw = qw + 512;

    for (int r = lane; r < 225; r += 32) sb[r] = rel_bias[r*NH + h];

#pragma unroll
    for (int i = 0; i < 32; i++) {
        int idx = lane + 32*i;
        int n = idx >> 4, dp = idx & 15;
        u32 u = *(const u32*)(vw + (size_t)n*768 + 2*dp);
        __nv_bfloat162 v2 = *(__nv_bfloat162*)&u;
        Vt[2*dp  ][n] = v2.x;
        Vt[2*dp+1][n] = v2.y;
    }
    __syncwarp();

    u32 aQ[2][4][4];
#pragma unroll
    for (int ks = 0; ks < 2; ks++) {
        const int kc = 16*ks + 2*tig;
#pragma unroll
        for (int mt = 0; mt < 4; mt++) {
            const __nv_bfloat16* q0 = qw + (size_t)(mt*16 + g)*768 + kc;
            aQ[ks][mt][0] = *(const u32*)(q0);
            aQ[ks][mt][1] = *(const u32*)(q0 + 8*768);
            aQ[ks][mt][2] = *(const u32*)(q0 + 8);
            aQ[ks][mt][3] = *(const u32*)(q0 + 8*768 + 8);
        }
    }

    float O[4][4][4];
#pragma unroll
    for (int a = 0; a < 4; a++)
#pragma unroll
        for (int bq = 0; bq < 4; bq++)
#pragma unroll
            for (int c = 0; c < 4; c++) O[a][bq][c] = 0.f;
    float mrow[8], lrow[8];
#pragma unroll
    for (int r = 0; r < 8; r++) { mrow[r] = -1e30f; lrow[r] = 0.f; }

#pragma unroll 1
    for (int ck = 0; ck < 2; ck++) {
        float S[4][4][4];
#pragma unroll
        for (int a = 0; a < 4; a++)
#pragma unroll
            for (int bq = 0; bq < 4; bq++)
#pragma unroll
                for (int c = 0; c < 4; c++) S[a][bq][c] = 0.f;

#pragma unroll
        for (int ks = 0; ks < 2; ks++) {
            const int kc = 16*ks + 2*tig;
            u32 bK[4][2];
#pragma unroll
            for (int nt = 0; nt < 4; nt++) {
                const __nv_bfloat16* k0 = kw + (size_t)(ck*32 + nt*8 + g)*768 + kc;
                bK[nt][0] = *(const u32*)(k0);
                bK[nt][1] = *(const u32*)(k0 + 8);
            }
#pragma unroll
            for (int mt = 0; mt < 4; mt++)
#pragma unroll
                for (int nt = 0; nt < 4; nt++)
                    mma_bf16(S[mt][nt], aQ[ks][mt], bK[nt]);
        }

#pragma unroll
        for (int mt = 0; mt < 4; mt++)
#pragma unroll
            for (int nt = 0; nt < 4; nt++)
#pragma unroll
                for (int rr = 0; rr < 2; rr++)
#pragma unroll
                    for (int e = 0; e < 2; e++) {
                        int di = 2*mt + rr - (4*ck + nt) + 7;
                        int dj = g - (2*tig + e) + 7;
                        S[mt][nt][rr*2+e] = S[mt][nt][rr*2+e] * 0.17677669529663687f
                                          + sb[di*15 + dj];
                    }

#pragma unroll
        for (int mt = 0; mt < 4; mt++)
#pragma unroll
            for (int rr = 0; rr < 2; rr++) {
                const int r8 = mt*2 + rr;
                float mloc = -1e30f;
#pragma unroll
                for (int nt = 0; nt < 4; nt++) {
                    mloc = fmaxf(mloc, S[mt][nt][rr*2]);
                    mloc = fmaxf(mloc, S[mt][nt][rr*2+1]);
                }
                mloc = fmaxf(mloc, __shfl_xor_sync(0xffffffffu, mloc, 1));
                mloc = fmaxf(mloc, __shfl_xor_sync(0xffffffffu, mloc, 2));
                float newm = fmaxf(mrow[r8], mloc);
                float fsc = __expf(mrow[r8] - newm);
                mrow[r8] = newm;
                float rsum = 0.f;
#pragma unroll
                for (int nt = 0; nt < 4; nt++) {
                    float p0 = __expf(S[mt][nt][rr*2]   - newm);
                    float p1 = __expf(S[mt][nt][rr*2+1] - newm);
                    S[mt][nt][rr*2] = p0; S[mt][nt][rr*2+1] = p1;
                    rsum += p0 + p1;
                }
                rsum += __shfl_xor_sync(0xffffffffu, rsum, 1);
                rsum += __shfl_xor_sync(0xffffffffu, rsum, 2);
                lrow[r8] = lrow[r8]*fsc + rsum;
#pragma unroll
                for (int nt2 = 0; nt2 < 4; nt2++) {
                    O[mt][nt2][rr*2]   *= fsc;
                    O[mt][nt2][rr*2+1] *= fsc;
                }
            }

#pragma unroll
        for (int ks2 = 0; ks2 < 2; ks2++) {
            u32 bV[4][2];
#pragma unroll
            for (int p = 0; p < 2; p++) {
                u32 vaddr = vtb + (u32)(((p*16 + v_dc)*72 + ck*32 + ks2*16 + v_dk) * 2);
                ldsm4(bV[2*p][0], bV[2*p][1], bV[2*p+1][0], bV[2*p+1][1], vaddr);
            }
#pragma unroll
            for (int mt = 0; mt < 4; mt++) {
                u32 pa[4];
                pa[0] = packbf(S[mt][2*ks2  ][0], S[mt][2*ks2  ][1]);
                pa[1] = packbf(S[mt][2*ks2  ][2], S[mt][2*ks2  ][3]);
                pa[2] = packbf(S[mt][2*ks2+1][0], S[mt][2*ks2+1][1]);
                pa[3] = packbf(S[mt][2*ks2+1][2], S[mt][2*ks2+1][3]);
#pragma unroll
                for (int nt2 = 0; nt2 < 4; nt2++)
                    mma_bf16(O[mt][nt2], pa, bV[nt2]);
            }
        }
    }

    float invl[8];
#pragma unroll
    for (int r = 0; r < 8; r++) invl[r] = 1.f / lrow[r];
    __nv_bfloat16* ob = o + (size_t)win * 64 * 256 + h * 32;
#pragma unroll
    for (int mt = 0; mt < 4; mt++)
#pragma unroll
        for (int nt2 = 0; nt2 < 4; nt2++) {
            __nv_bfloat16* p0 = ob + (size_t)(mt*16 + g)*256 + nt2*8 + 2*tig;
            *(u32*)(p0)         = packbf(O[mt][nt2][0]*invl[2*mt],   O[mt][nt2][1]*invl[2*mt]);
            *(u32*)(p0 + 8*256) = packbf(O[mt][nt2][2]*invl[2*mt+1], O[mt][nt2][3]*invl[2*mt+1]);
        }
}

// -------------------- SE gate from completed pooled sums --------------------
__global__ void __launch_bounds__(256) k_pool_gate(const float* __restrict__ part,
                                                   const float* __restrict__ w1,
                                                   const float* __restrict__ b1,
                                                   const float* __restrict__ w2,
                                                   const float* __restrict__ b2,
                                                   float* __restrict__ gate) {
    int b = blockIdx.x;
    float pooled = part[b*256 + threadIdx.x] * (1.f / (float)TOK_PER_B);
    __shared__ float sp[256];
    __shared__ float hid[16];
    sp[threadIdx.x] = pooled;
    __syncthreads();
    if (threadIdx.x < 16) {
        float a = b1[threadIdx.x];
        for (int c = 0; c < 256; c++) a = fmaf(sp[c], w1[c*16 + threadIdx.x], a);
        hid[threadIdx.x] = fmaxf(a, 0.f);
    }
    __syncthreads();
    float g = b2[threadIdx.x];
#pragma unroll
    for (int j = 0; j < 16; j++) g = fmaf(hid[j], w2[j*256 + threadIdx.x], g);
    gate[b*256 + threadIdx.x] = 1.f / (1.f + __expf(-g));
}

// ---------------------------------------------------------------------------
extern "C" void kernel_launch(void* const* d_in, const int* in_sizes, int n_in,
                              void* d_out, int out_size) {
    const float* x      = (const float*)d_in[0];
    const float* n1_g   = (const float*)d_in[1];
    const float* n1_b   = (const float*)d_in[2];
    const float* qkv_w  = (const float*)d_in[3];
    const float* qkv_b  = (const float*)d_in[4];
    const float* proj_w = (const float*)d_in[5];
    const float* proj_b = (const float*)d_in[6];
    const float* rel_b  = (const float*)d_in[7];
    const float* se_w1  = (const float*)d_in[8];
    const float* se_b1  = (const float*)d_in[9];
    const float* se_w2  = (const float*)d_in[10];
    const float* se_b2  = (const float*)d_in[11];
    const float* n3_g   = (const float*)d_in[12];
    const float* n3_b   = (const float*)d_in[13];
    const float* mlp_w1 = (const float*)d_in[14];
    const float* mlp_b1 = (const float*)d_in[15];
    const float* mlp_w2 = (const float*)d_in[16];
    const float* mlp_b2 = (const float*)d_in[17];
    float* out = (float*)d_out;

    float *wins, *hbuf, *big, *part, *gate, *wb;
    cudaGetSymbolAddress((void**)&wins, g_wins);
    cudaGetSymbolAddress((void**)&hbuf, g_h);
    cudaGetSymbolAddress((void**)&big,  g_big);
    cudaGetSymbolAddress((void**)&part, g_part);
    cudaGetSymbolAddress((void**)&gate, g_gate);
    cudaGetSymbolAddress((void**)&wb,   g_wb);

    __nv_bfloat16* wbf   = (__nv_bfloat16*)wb;
    __nv_bfloat16* qkvW  = wbf;            // [768,256]
    __nv_bfloat16* projW = wbf + 196608;   // [256,256]
    __nv_bfloat16* w1W   = wbf + 262144;   // [1024,256]
    __nv_bfloat16* w2W   = wbf + 524288;   // [256,1024]
    __nv_bfloat16* bigb  = (__nv_bfloat16*)big;
    __nv_bfloat16* hb    = (__nv_bfloat16*)hbuf;

    cudaFuncSetAttribute(k_gemm_smA,    cudaFuncAttributeMaxDynamicSharedMemorySize, SMA_SMEM);
    cudaFuncSetAttribute(k_gemm_sA_rev, cudaFuncAttributeMaxDynamicSharedMemorySize, SR_SMEM);

    dim3 b328(32, 8);
    dim3 gtr(WW_/32, HH, BATCH*8);

    // ncu captures launch #4 -> QKV GEMM goes 4th.
    k_winpart<<<gtr, b328>>>(x, wins, part);                              // 1
    k_wprep2<<<448, b328>>>(qkv_w, qkvW, 256, 768, 192,                   // 2 (qkv + w1)
                            mlp_w1, w1W, 256, 1024);
    k_wprep2<<<320, b328>>>(proj_w, projW, 256, 256, 64,                  // 3 (proj + w2)
                            mlp_w2, w2W, 1024, 256);
    k_gemm_smA<<<NTOK/256, 256, SMA_SMEM>>>(wins, 0, n1_g, n1_b, nullptr, // 4 <- profiled
                                            qkvW, qkv_b, nullptr,
                                            bigb, 1, 0, 768, nullptr);
    k_attn_tc<<<dim3(NWIN, 2), 128>>>(bigb, rel_b, hb);
    k_gemm_smA<<<NTOK/256, 256, SMA_SMEM>>>(hb, 1, nullptr, nullptr, nullptr,
                                            projW, proj_b, wins,
                                            wins, 0, 0, 256, part);
    k_pool_gate<<<BATCH, 256>>>(part, se_w1, se_b1, se_w2, se_b2, gate);
    k_gemm_smA<<<NTOK/256, 256, SMA_SMEM>>>(wins, 0, n3_g, n3_b, gate,
                                            w1W, mlp_b1, nullptr,
                                            bigb, 1, 1, 1024, nullptr);
    k_gemm_sA_rev<<<NTOK/256, 256, SR_SMEM>>>(bigb, w2W, mlp_b2, wins, gate, out);
}

// round 14
// speedup vs baseline: 1.0936x; 1.0921x over previous
#include <cuda_runtime.h>
#include <cuda_bf16.h>
#include <cstdint>
#include <math.h>

// ---------------------------------------------------------------------------
// HATBlock — Round 14: QKV GEMM + window attention fused into one kernel
// (head-packed weights, Q/K/Vt tiles in smem, no qkv gmem round trip).
// B=4, C=256, H=W=192, WS=8, NH=8, HD=32
// ---------------------------------------------------------------------------

#define BATCH 4
#define DIM   256
#define HH    192
#define WW_   192
#define NWH   24
#define NWIN  (BATCH*NWH*NWH)   // 2304
#define NTOK  (NWIN*64)         // 147456
#define NH    8
#define TOK_PER_B (HH*WW_)      // 36864

typedef unsigned long long u64;
typedef unsigned int u32;

// -------------------- scratch (device globals; no runtime alloc) -----------
__device__ float g_wins[(size_t)NTOK*256];     // wins / y (fp32)
__device__ float g_h   [(size_t)NTOK*256];     // attn-out bf16 alias
__device__ float g_big [(size_t)NTOK*512];     // mlp hidden as bf16
__device__ float g_part[1024];                 // pooled sums [B,256]
__device__ float g_gate[BATCH*256];
__device__ float g_wb  [786432/2];             // bf16 weights, transposed [N,K]

__device__ __forceinline__ float gelu_exact(float x) {
    return 0.5f * x * (1.0f + erff(x * 0.70710678118654752f));
}

__device__ __forceinline__ void cp_async16(void* smem, const void* gmem) {
    unsigned s = (unsigned)__cvta_generic_to_shared(smem);
    asm volatile("cp.async.ca.shared.global [%0], [%1], 16;" :: "r"(s), "l"(gmem));
}
__device__ __forceinline__ void cp_commit() { asm volatile("cp.async.commit_group;"); }
__device__ __forceinline__ void cp_wait0()  { asm volatile("cp.async.wait_group 0;" ::: "memory"); }
__device__ __forceinline__ void cp_wait1()  { asm volatile("cp.async.wait_group 1;" ::: "memory"); }
__device__ __forceinline__ void cp_wait2()  { asm volatile("cp.async.wait_group 2;" ::: "memory"); }

__device__ __forceinline__ void mma_bf16(float* c, const u32* a, const u32* b) {
    asm volatile(
        "mma.sync.aligned.m16n8k16.row.col.f32.bf16.bf16.f32 "
        "{%0,%1,%2,%3},{%4,%5,%6,%7},{%8,%9},{%0,%1,%2,%3};"
        : "+f"(c[0]), "+f"(c[1]), "+f"(c[2]), "+f"(c[3])
        : "r"(a[0]), "r"(a[1]), "r"(a[2]), "r"(a[3]), "r"(b[0]), "r"(b[1]));
}

__device__ __forceinline__ void ldsm4(u32& r0, u32& r1, u32& r2, u32& r3, u32 addr) {
    asm volatile("ldmatrix.sync.aligned.m8n8.x4.shared.b16 {%0,%1,%2,%3}, [%4];"
                 : "=r"(r0), "=r"(r1), "=r"(r2), "=r"(r3) : "r"(addr));
}

__device__ __forceinline__ u32 packbf(float a, float b) {
    __nv_bfloat162 t = __float22bfloat162_rn(make_float2(a, b));
    return *(u32*)&t;
}

// -------------------- weight prep: fp32 [K,N] -> bf16 [N,K] (+row remap) ---
__device__ __forceinline__ void wprep_body(const float* in, __nv_bfloat16* out,
                                           int K, int N, int n0, int k0, int outRow0) {
    __shared__ float tile[32][33];
    for (int r = threadIdx.y; r < 32; r += 8)
        tile[r][threadIdx.x] = in[(size_t)(k0 + r) * N + n0 + threadIdx.x];
    __syncthreads();
    for (int r = threadIdx.y; r < 32; r += 8)
        out[(size_t)(outRow0 + r) * K + k0 + threadIdx.x] = __float2bfloat16_rn(tile[threadIdx.x][r]);
}

// two weights in one launch; remapA=1 packs qkv head-major: [8][96][256]
__global__ void k_wprep2(const float* __restrict__ inA, __nv_bfloat16* __restrict__ outA,
                         int KA, int NA, int nblkA, int remapA,
                         const float* __restrict__ inB, __nv_bfloat16* __restrict__ outB,
                         int KB, int NB) {
    int blk = blockIdx.x;
    if (blk < nblkA) {
        int w = NA / 32;
        int n0 = (blk % w) * 32, k0 = (blk / w) * 32;
        int outRow0 = n0;
        if (remapA) {
            int part = n0 >> 8, h = (n0 & 255) >> 5;
            outRow0 = h * 96 + part * 32;
        }
        wprep_body(inA, outA, KA, NA, n0, k0, outRow0);
    } else {
        blk -= nblkA;
        int w = NB / 32;
        int n0 = (blk % w) * 32, k0 = (blk / w) * 32;
        wprep_body(inB, outB, KB, NB, n0, k0, n0);
    }
}

// -------------------- window partition (+ zero pooled sums) ----------------
__global__ void k_winpart(const float* __restrict__ x, float* __restrict__ wins,
                          float* __restrict__ part) {
    int w0 = blockIdx.x * 32, hh = blockIdx.y;
    int b = blockIdx.z >> 3, c0 = (blockIdx.z & 7) * 32;
    if (blockIdx.x == 0 && blockIdx.y == 0 && blockIdx.z == 0) {
        int t = threadIdx.y * 32 + threadIdx.x;
#pragma unroll
        for (int i = 0; i < 4; i++) part[t + 256*i] = 0.f;
    }
    __shared__ float tile[32][33];
    for (int cc = threadIdx.y; cc < 32; cc += 8)
        tile[cc][threadIdx.x] =
            x[(((size_t)b*256 + c0 + cc)*HH + hh)*WW_ + w0 + threadIdx.x];
    __syncthreads();
    int hw = hh >> 3, i = hh & 7;
    for (int wi = threadIdx.y; wi < 32; wi += 8) {
        int w = w0 + wi, ww = w >> 3, j = w & 7;
        size_t t = (((size_t)b*NWH + hw)*NWH + ww)*64 + i*8 + j;
        wins[t*256 + c0 + threadIdx.x] = tile[threadIdx.x][wi];
    }
}

// ============================================================================
// Fused QKV GEMM + window attention.  CTA = 256 tokens (4 windows), 8 warps.
// Per head h: GEMM 256x96x256 (A = LN(wins) cached smem; W head-packed,
// 2-stage cp.async ring of 64-K chunks) -> Q,K smem tile + V transposed tile;
// then 8 warps = 4 windows x 2 half-windows do attention; O -> hb bf16 gmem.
// smem: Ab 256x264 bf16 @0; QK 256x72 bf16 @135168; Vt 32x264 bf16 @172032;
//       ring 2x13824 @188928; packed bias 768f @216576; bias tables @219648.
// ============================================================================
#define F_AB_STR 264
#define F_QK_STR 72
#define F_VT_STR 264
#define FS_QK   135168
#define FS_VT   172032
#define FS_RING 188928
#define FS_RSTG 13824
#define FS_PB   216576
#define FS_SB   219648
#define FS_SMEM 226880

__global__ void __launch_bounds__(256, 1)
k_fused_qkv_attn(const float* __restrict__ Ain,
                 const float* __restrict__ lng, const float* __restrict__ lnb,
                 const __nv_bfloat16* __restrict__ Wt,   // packed [8][96][256]
                 const float* __restrict__ qkv_b,
                 const float* __restrict__ rel_bias,
                 __nv_bfloat16* __restrict__ hb)
{
    extern __shared__ char smem[];
    __nv_bfloat16* Ab  = (__nv_bfloat16*)smem;
    __nv_bfloat16* qk  = (__nv_bfloat16*)(smem + FS_QK);
    __nv_bfloat16* vT  = (__nv_bfloat16*)(smem + FS_VT);
    float* pb = (float*)(smem + FS_PB);
    float* sbt = (float*)(smem + FS_SB);
    const u32 sbase = (u32)__cvta_generic_to_shared(smem);

    const int tid = threadIdx.x, lane = tid & 31, wid = tid >> 5;
    const int g = lane >> 2, tig = lane & 3;
    const int m0 = blockIdx.x * 256;

    const int a_dr = (lane & 7) | (((lane >> 3) & 1) << 3);
    const int a_dk = (lane >> 4) << 3;
    const int quad = lane >> 3;
    const int b_dc = (lane & 7) + ((quad & 2) ? 8 : 0);
    const int b_dk = (quad & 1) << 3;

    // ring prefetch of first two W chunks
    auto fillW = [&](int hc) {
        __nv_bfloat16* Bs = (__nv_bfloat16*)(smem + FS_RING + (hc & 1) * FS_RSTG);
        const __nv_bfloat16* Wg = Wt + (size_t)(hc >> 2) * 96 * 256 + (hc & 3) * 64;
#pragma unroll
        for (int i = 0; i < 3; i++) {
            int idx = tid + 256*i;          // 0..767
            int row = idx >> 3, seg = idx & 7;
            cp_async16(Bs + row*F_QK_STR + seg*8, Wg + (size_t)row*256 + seg*8);
        }
        cp_commit();
    };
    fillW(0); fillW(1);

    // packed bias + rel-bias tables
    for (int j = tid; j < 768; j += 256) {
        int h = j / 96, r = j % 96, part = r >> 5;
        pb[j] = qkv_b[part*256 + h*32 + (r & 31)];
    }
    for (int idx = tid; idx < 8*225; idx += 256) {
        int hh = idx / 225, rr = idx % 225;
        sbt[hh*226 + rr] = rel_bias[rr*NH + hh];
    }

    // ---- fused LN of A tile (fp32 gmem -> bf16 smem) ----
    {
        const float* Ag = Ain + (size_t)m0 * 256;
        float lg[8], lb[8];
#pragma unroll
        for (int j = 0; j < 8; j++) {
            int c = lane*8 + j;
            lg[j] = lng[c]; lb[j] = lnb[c];
        }
#pragma unroll 1
        for (int i = 0; i < 32; i++) {
            int r = wid*32 + i;
            const float4* rp = (const float4*)(Ag + (size_t)r * 256 + lane*8);
            float4 va = rp[0], vb = rp[1];
            float v[8] = {va.x, va.y, va.z, va.w, vb.x, vb.y, vb.z, vb.w};
            float s = 0.f, s2 = 0.f;
#pragma unroll
            for (int j = 0; j < 8; j++) { s += v[j]; s2 += v[j]*v[j]; }
#pragma unroll
            for (int o = 16; o; o >>= 1) {
                s  += __shfl_xor_sync(0xffffffffu, s,  o);
                s2 += __shfl_xor_sync(0xffffffffu, s2, o);
            }
            float mean = s * (1.f/256.f);
            float var  = s2 * (1.f/256.f) - mean*mean;
            float inv  = rsqrtf(var + 1e-5f);
#pragma unroll
            for (int k = 0; k < 4; k++) {
                float n0 = (v[2*k  ]-mean)*inv*lg[2*k  ] + lb[2*k  ];
                float n1 = (v[2*k+1]-mean)*inv*lg[2*k+1] + lb[2*k+1];
                *(u32*)&Ab[r*F_AB_STR + lane*8 + 2*k] = packbf(n0, n1);
            }
        }
        __syncthreads();
    }

    const int wi = wid >> 1, hf = wid & 1;   // attention task mapping

#pragma unroll 1
    for (int h = 0; h < 8; h++) {
        // ---- GEMM 256x96x256 for this head ----
        float acc[2][12][4];
#pragma unroll
        for (int i = 0; i < 2; i++)
#pragma unroll
            for (int j = 0; j < 12; j++)
#pragma unroll
                for (int q = 0; q < 4; q++) acc[i][j][q] = 0.f;

#pragma unroll 1
        for (int ck = 0; ck < 4; ck++) {
            const int hc = h*4 + ck;
            if (hc == 31) cp_wait0(); else cp_wait1();
            __syncthreads();
            const u32 rb = sbase + FS_RING + (u32)(hc & 1) * FS_RSTG;
#pragma unroll
            for (int ks = 0; ks < 4; ks++) {
                const int kb = ck*64 + ks*16;
                u32 af[2][4], bf[12][2];
#pragma unroll
                for (int mt = 0; mt < 2; mt++) {
                    u32 aaddr = sbase + (u32)(((wid*32 + mt*16 + a_dr)*F_AB_STR + kb + a_dk) * 2);
                    ldsm4(af[mt][0], af[mt][1], af[mt][2], af[mt][3], aaddr);
                }
#pragma unroll
                for (int p = 0; p < 6; p++) {
                    u32 baddr = rb + (u32)(((p*16 + b_dc)*F_QK_STR + ks*16 + b_dk) * 2);
                    ldsm4(bf[2*p][0], bf[2*p][1], bf[2*p+1][0], bf[2*p+1][1], baddr);
                }
#pragma unroll
                for (int mt = 0; mt < 2; mt++)
#pragma unroll
                    for (int nt = 0; nt < 12; nt++)
                        mma_bf16(acc[mt][nt], af[mt], bf[nt]);
            }
            __syncthreads();
            if (hc + 2 < 32) fillW(hc + 2);
        }

        // ---- epilogue: Q,K -> qk tile; V -> transposed vT tile ----
#pragma unroll
        for (int nt = 0; nt < 12; nt++) {
            int colj = nt*8 + 2*tig;
            float b0 = pb[h*96 + colj], b1 = pb[h*96 + colj + 1];
#pragma unroll
            for (int mt = 0; mt < 2; mt++) {
                int r0 = wid*32 + mt*16 + g, r1 = r0 + 8;
                float v00 = acc[mt][nt][0] + b0, v01 = acc[mt][nt][1] + b1;
                float v10 = acc[mt][nt][2] + b0, v11 = acc[mt][nt][3] + b1;
                if (nt < 8) {
                    *(u32*)&qk[r0*F_QK_STR + colj] = packbf(v00, v01);
                    *(u32*)&qk[r1*F_QK_STR + colj] = packbf(v10, v11);
                } else {
                    int c = colj - 64;
                    vT[c*F_VT_STR + r0]     = __float2bfloat16_rn(v00);
                    vT[(c+1)*F_VT_STR + r0] = __float2bfloat16_rn(v01);
                    vT[c*F_VT_STR + r1]     = __float2bfloat16_rn(v10);
                    vT[(c+1)*F_VT_STR + r1] = __float2bfloat16_rn(v11);
                }
            }
        }
        __syncthreads();

        // ---- attention: warp = (window wi, half hf) -> 32 q-rows x 64 keys
        const float* sbh = sbt + h*226;
        u32 aQ[2][2][4];
#pragma unroll
        for (int ks = 0; ks < 2; ks++)
#pragma unroll
            for (int mt = 0; mt < 2; mt++) {
                u32 aaddr = sbase + FS_QK +
                    (u32)(((wi*64 + hf*32 + mt*16 + a_dr)*F_QK_STR + ks*16 + a_dk) * 2);
                ldsm4(aQ[ks][mt][0], aQ[ks][mt][1], aQ[ks][mt][2], aQ[ks][mt][3], aaddr);
            }

        float S[2][8][4];
#pragma unroll
        for (int i = 0; i < 2; i++)
#pragma unroll
            for (int j = 0; j < 8; j++)
#pragma unroll
                for (int q = 0; q < 4; q++) S[i][j][q] = 0.f;

#pragma unroll
        for (int ks = 0; ks < 2; ks++) {
            u32 bK[8][2];
#pragma unroll
            for (int p = 0; p < 4; p++) {
                u32 baddr = sbase + FS_QK +
                    (u32)(((wi*64 + p*16 + b_dc)*F_QK_STR + 32 + ks*16 + b_dk) * 2);
                ldsm4(bK[2*p][0], bK[2*p][1], bK[2*p+1][0], bK[2*p+1][1], baddr);
            }
#pragma unroll
            for (int mt = 0; mt < 2; mt++)
#pragma unroll
                for (int nt = 0; nt < 8; nt++)
                    mma_bf16(S[mt][nt], aQ[ks][mt], bK[nt]);
        }

        // scale + relative bias
#pragma unroll
        for (int mt = 0; mt < 2; mt++)
#pragma unroll
            for (int nt = 0; nt < 8; nt++)
#pragma unroll
                for (int rr = 0; rr < 2; rr++)
#pragma unroll
                    for (int e = 0; e < 2; e++) {
                        int di = hf*4 + mt*2 + rr - nt + 7;
                        int dj = g - (2*tig + e) + 7;
                        S[mt][nt][rr*2+e] = S[mt][nt][rr*2+e] * 0.17677669529663687f
                                          + sbh[di*15 + dj];
                    }

        // softmax (single 64-key chunk)
        float lrow[4];
#pragma unroll
        for (int mt = 0; mt < 2; mt++)
#pragma unroll
            for (int rr = 0; rr < 2; rr++) {
                float mx = -1e30f;
#pragma unroll
                for (int nt = 0; nt < 8; nt++) {
                    mx = fmaxf(mx, S[mt][nt][rr*2]);
                    mx = fmaxf(mx, S[mt][nt][rr*2+1]);
                }
                mx = fmaxf(mx, __shfl_xor_sync(0xffffffffu, mx, 1));
                mx = fmaxf(mx, __shfl_xor_sync(0xffffffffu, mx, 2));
                float sum = 0.f;
#pragma unroll
                for (int nt = 0; nt < 8; nt++) {
                    float p0 = __expf(S[mt][nt][rr*2]   - mx);
                    float p1 = __expf(S[mt][nt][rr*2+1] - mx);
                    S[mt][nt][rr*2] = p0; S[mt][nt][rr*2+1] = p1;
                    sum += p0 + p1;
                }
                sum += __shfl_xor_sync(0xffffffffu, sum, 1);
                sum += __shfl_xor_sync(0xffffffffu, sum, 2);
                lrow[mt*2 + rr] = sum;
            }

        // O = P V
        float O[2][4][4];
#pragma unroll
        for (int i = 0; i < 2; i++)
#pragma unroll
            for (int j = 0; j < 4; j++)
#pragma unroll
                for (int q = 0; q < 4; q++) O[i][j][q] = 0.f;
#pragma unroll
        for (int ks2 = 0; ks2 < 4; ks2++) {
            u32 bV[4][2];
#pragma unroll
            for (int p = 0; p < 2; p++) {
                u32 vaddr = sbase + FS_VT +
                    (u32)(((p*16 + b_dc)*F_VT_STR + wi*64 + ks2*16 + b_dk) * 2);
                ldsm4(bV[2*p][0], bV[2*p][1], bV[2*p+1][0], bV[2*p+1][1], vaddr);
            }
#pragma unroll
            for (int mt = 0; mt < 2; mt++) {
                u32 pa[4];
                pa[0] = packbf(S[mt][2*ks2  ][0], S[mt][2*ks2  ][1]);
                pa[1] = packbf(S[mt][2*ks2  ][2], S[mt][2*ks2  ][3]);
                pa[2] = packbf(S[mt][2*ks2+1][0], S[mt][2*ks2+1][1]);
                pa[3] = packbf(S[mt][2*ks2+1][2], S[mt][2*ks2+1][3]);
#pragma unroll
                for (int nt2 = 0; nt2 < 4; nt2++)
                    mma_bf16(O[mt][nt2], pa, bV[nt2]);
            }
        }

        // normalize + store to hb
#pragma unroll
        for (int mt = 0; mt < 2; mt++) {
            float inv0 = 1.f / lrow[mt*2], inv1 = 1.f / lrow[mt*2 + 1];
            size_t rg = (size_t)m0 + wi*64 + hf*32 + mt*16 + g;
#pragma unroll
            for (int nt2 = 0; nt2 < 4; nt2++) {
                __nv_bfloat16* p0 = hb + rg*256 + h*32 + nt2*8 + 2*tig;
                *(u32*)(p0)         = packbf(O[mt][nt2][0]*inv0, O[mt][nt2][1]*inv0);
                *(u32*)(p0 + 8*256) = packbf(O[mt][nt2][2]*inv1, O[mt][nt2][3]*inv1);
            }
        }
    }
}

// ============================================================================
// GEMM 1 (proj / MLP1): CTA 256x128, 8 warps, warp 64x64, K chunk 32.
// ============================================================================
#define AB_STR 264
#define B_STR  40
#define SMA_BR   135168
#define SMA_SCOL 176128
#define SMA_SMEM 176640

__global__ void __launch_bounds__(256, 1)
k_gemm_smA(const void* __restrict__ Ain, int a_bf16,
           const float* __restrict__ lng, const float* __restrict__ lnb,
           const float* __restrict__ gate,
           const __nv_bfloat16* __restrict__ Wt,
           const float* __restrict__ bias,
           const float* __restrict__ R,
           void* __restrict__ Cout, int c_bf16, int act,
           int Nfull, float* __restrict__ pool)
{
    extern __shared__ char smem[];
    __nv_bfloat16* Ab = (__nv_bfloat16*)smem;
    char*  Bring = smem + SMA_BR;
    float* scol = (float*)(smem + SMA_SCOL);
    const u32 sbase = (u32)__cvta_generic_to_shared(smem);

    const int tid = threadIdx.x, lane = tid & 31, wid = tid >> 5;
    const int g = lane >> 2, tig = lane & 3;
    const int arow = (wid & 3) * 64;
    const int bcol = (wid >> 2) * 64;
    const int m0 = blockIdx.x * 256;
    const int b  = m0 / TOK_PER_B;

    const int a_dr = (lane & 7) | (((lane >> 3) & 1) << 3);
    const int a_dk = (lane >> 4) << 3;
    const int quad = lane >> 3;
    const int b_dc = (lane & 7) + ((quad & 2) ? 8 : 0);
    const int b_dk = (quad & 1) << 3;

    if (a_bf16) {
        const __nv_bfloat16* Ag = (const __nv_bfloat16*)Ain + (size_t)m0 * 256;
#pragma unroll
        for (int i = 0; i < 32; i++) {
            int idx = tid + 256*i;
            int r = idx >> 5, c8 = idx & 31;
            cp_async16(Ab + r*AB_STR + c8*8, Ag + (size_t)r*256 + c8*8);
        }
        cp_commit();
    } else {
        const float* Ag = (const float*)Ain + (size_t)m0 * 256;
        const float* gp = gate ? (gate + b*256) : nullptr;
        float gv[8], lg[8], lb[8];
#pragma unroll
        for (int j = 0; j < 8; j++) {
            int c = lane*8 + j;
            gv[j] = gp ? gp[c] : 1.f;
            lg[j] = lng[c]; lb[j] = lnb[c];
        }
#pragma unroll 1
        for (int i = 0; i < 32; i++) {
            int r = wid*32 + i;
            const float4* rp = (const float4*)(Ag + (size_t)r * 256 + lane*8);
            float4 va = rp[0], vb = rp[1];
            float v[8] = {va.x, va.y, va.z, va.w, vb.x, vb.y, vb.z, vb.w};
            float s = 0.f, s2 = 0.f;
#pragma unroll
            for (int j = 0; j < 8; j++) {
                v[j] *= gv[j]; s += v[j]; s2 += v[j]*v[j];
            }
#pragma unroll
            for (int o = 16; o; o >>= 1) {
                s  += __shfl_xor_sync(0xffffffffu, s,  o);
                s2 += __shfl_xor_sync(0xffffffffu, s2, o);
            }
            float mean = s * (1.f/256.f);
            float var  = s2 * (1.f/256.f) - mean*mean;
            float inv  = rsqrtf(var + 1e-5f);
#pragma unroll
            for (int k = 0; k < 4; k++) {
                float n0 = (v[2*k  ]-mean)*inv*lg[2*k  ] + lb[2*k  ];
                float n1 = (v[2*k+1]-mean)*inv*lg[2*k+1] + lb[2*k+1];
                *(u32*)&Ab[r*AB_STR + lane*8 + 2*k] = packbf(n0, n1);
            }
        }
        __syncthreads();
    }

    const int NY = Nfull >> 7;
    const int KT = 8;
    const int TOT = NY * KT;

    auto fillB = [&](int c) {
        int ny2 = c >> 3, kt2 = c & 7, st = c & 3;
        __nv_bfloat16* Bs = (__nv_bfloat16*)(Bring + st*10240);
        const __nv_bfloat16* Wg = Wt + (size_t)(ny2*128) * 256 + kt2*32;
#pragma unroll
        for (int i = 0; i < 2; i++) {
            int idx = tid + 256*i;
            int row = idx >> 2, seg = idx & 3;
            cp_async16(Bs + row*B_STR + seg*8, Wg + (size_t)row*256 + seg*8);
        }
        cp_commit();
    };
    fillB(0); fillB(1); fillB(2);

    int ci = 0;
    for (int ny = 0; ny < NY; ny++) {
        float acc[4][8][4];
#pragma unroll
        for (int i = 0; i < 4; i++)
#pragma unroll
            for (int j = 0; j < 8; j++)
#pragma unroll
                for (int q = 0; q < 4; q++) acc[i][j][q] = 0.f;

        for (int kt = 0; kt < KT; kt++, ci++) {
            cp_wait2();
            __syncthreads();
            const u32 bsb = sbase + SMA_BR + (u32)(ci & 3)*10240;
#pragma unroll
            for (int ks = 0; ks < 2; ks++) {
                const int kb = kt*32 + ks*16;
                u32 af[4][4], bf[8][2];
#pragma unroll
                for (int mt = 0; mt < 4; mt++) {
                    u32 aaddr = sbase + (u32)(((arow + mt*16 + a_dr)*AB_STR + kb + a_dk) * 2);
                    ldsm4(af[mt][0], af[mt][1], af[mt][2], af[mt][3], aaddr);
                }
#pragma unroll
                for (int p = 0; p < 4; p++) {
                    u32 baddr = bsb + (u32)(((bcol + p*16 + b_dc)*B_STR + ks*16 + b_dk) * 2);
                    ldsm4(bf[2*p][0], bf[2*p][1], bf[2*p+1][0], bf[2*p+1][1], baddr);
                }
#pragma unroll
                for (int mt = 0; mt < 4; mt++)
#pragma unroll
                    for (int nt = 0; nt < 8; nt++)
                        mma_bf16(acc[mt][nt], af[mt], bf[nt]);
            }
            if (ci + 3 < TOT) fillB(ci + 3);
            else cp_commit();
        }

        const int ncol0 = ny * 128;
        if (c_bf16) {
            __nv_bfloat16* Cb = (__nv_bfloat16*)Cout;
#pragma unroll
            for (int nt = 0; nt < 8; nt++) {
                int colG = ncol0 + bcol + nt*8 + 2*tig;
                float b0 = bias[colG], b1 = bias[colG + 1];
#pragma unroll
                for (int mt = 0; mt < 4; mt++) {
                    size_t r0 = (size_t)m0 + arow + mt*16 + g;
                    size_t r1 = r0 + 8;
                    float v00 = acc[mt][nt][0] + b0, v01 = acc[mt][nt][1] + b1;
                    float v10 = acc[mt][nt][2] + b0, v11 = acc[mt][nt][3] + b1;
                    if (act) {
                        v00 = gelu_exact(v00); v01 = gelu_exact(v01);
                        v10 = gelu_exact(v10); v11 = gelu_exact(v11);
                    }
                    *(u32*)((__nv_bfloat16*)Cb + r0*Nfull + colG) = packbf(v00, v01);
                    *(u32*)((__nv_bfloat16*)Cb + r1*Nfull + colG) = packbf(v10, v11);
                }
            }
        } else {
            float* Cf = (float*)Cout;
            float psum[8][2];
#pragma unroll
            for (int nt = 0; nt < 8; nt++) { psum[nt][0] = 0.f; psum[nt][1] = 0.f; }
#pragma unroll
            for (int nt = 0; nt < 8; nt++) {
                int colG = ncol0 + bcol + nt*8 + 2*tig;
                float b0 = bias[colG], b1 = bias[colG + 1];
#pragma unroll
                for (int mt = 0; mt < 4; mt++) {
                    size_t r0 = (size_t)m0 + arow + mt*16 + g;
                    size_t r1 = r0 + 8;
                    float2 q0 = *(const float2*)(R + r0*Nfull + colG);
                    float2 q1 = *(const float2*)(R + r1*Nfull + colG);
                    float v00 = acc[mt][nt][0] + b0 + q0.x, v01 = acc[mt][nt][1] + b1 + q0.y;
                    float v10 = acc[mt][nt][2] + b0 + q1.x, v11 = acc[mt][nt][3] + b1 + q1.y;
                    *(float2*)(Cf + r0*Nfull + colG) = make_float2(v00, v01);
                    *(float2*)(Cf + r1*Nfull + colG) = make_float2(v10, v11);
                    psum[nt][0] += v00 + v10; psum[nt][1] += v01 + v11;
                }
            }
            if (pool) {
                __syncthreads();
                if (tid < 128) scol[tid] = 0.f;
                __syncthreads();
#pragma unroll
                for (int nt = 0; nt < 8; nt++) {
                    int colL = bcol + nt*8 + 2*tig;
                    atomicAdd(&scol[colL],     psum[nt][0]);
                    atomicAdd(&scol[colL + 1], psum[nt][1]);
                }
                __syncthreads();
                if (tid < 128) atomicAdd(pool + b*256 + ncol0 + tid, scol[tid]);
                __syncthreads();
            }
        }
    }
}

// ============================================================================
// GEMM 2 (MLP2) + fused window-reverse (256 tokens = 4 windows per CTA).
// ============================================================================
#define SR_AST 20480
#define SR_BOFF 61440
#define SR_BST 10240
#define SR_STAGE 92160
#define SR_SMEM 224256
__global__ void __launch_bounds__(256, 1)
k_gemm_sA_rev(const __nv_bfloat16* __restrict__ Ain,
              const __nv_bfloat16* __restrict__ Wt,
              const float* __restrict__ bias,
              const float* __restrict__ R,
              const float* __restrict__ gate,
              float* __restrict__ out)
{
    extern __shared__ char smem[];
    const u32 sbase = (u32)__cvta_generic_to_shared(smem);
    float* sbuf = (float*)(smem + SR_STAGE);

    const int tid = threadIdx.x, lane = tid & 31, wid = tid >> 5;
    const int g = lane >> 2, tig = lane & 3;
    const int arow = (wid & 3) * 64;
    const int bcol = (wid >> 2) * 64;
    const int m0 = blockIdx.x * 256;
    const int b  = m0 / TOK_PER_B;

    const int win0 = m0 >> 6;
    const int rem  = win0 - b * (NWH*NWH);
    const int hw8  = (rem / NWH) * 8;
    const int w0g  = (rem % NWH) * 8;

    const int a_dr = (lane & 7) | (((lane >> 3) & 1) << 3);
    const int a_dk = (lane >> 4) << 3;
    const int quad = lane >> 3;
    const int b_dc = (lane & 7) + ((quad & 2) ? 8 : 0);
    const int b_dk = (quad & 1) << 3;

    const int KT = 32, NY = 2, TOT = 64;
    const __nv_bfloat16* Ag = Ain + (size_t)m0 * 1024;

    auto fillC = [&](int c) {
        int ny2 = c >> 5, kt2 = c & 31, st = c % 3;
        __nv_bfloat16* As = (__nv_bfloat16*)(smem + st*SR_AST);
        __nv_bfloat16* Bs = (__nv_bfloat16*)(smem + SR_BOFF + st*SR_BST);
        const __nv_bfloat16* Wg = Wt + (size_t)(ny2*128) * 1024 + kt2*32;
        const __nv_bfloat16* Ac = Ag + kt2*32;
#pragma unroll
        for (int i = 0; i < 4; i++) {
            int idx = tid + 256*i;
            int row = idx >> 2, seg = idx & 3;
            cp_async16(As + row*B_STR + seg*8, Ac + (size_t)row*1024 + seg*8);
        }
#pragma unroll
        for (int i = 0; i < 2; i++) {
            int idx = tid + 256*i;
            int row = idx >> 2, seg = idx & 3;
            cp_async16(Bs + row*B_STR + seg*8, Wg + (size_t)row*1024 + seg*8);
        }
        cp_commit();
    };
    fillC(0); fillC(1);

    int ci = 0;
    for (int ny = 0; ny < NY; ny++) {
        float acc[4][8][4];
#pragma unroll
        for (int i = 0; i < 4; i++)
#pragma unroll
            for (int j = 0; j < 8; j++)
#pragma unroll
                for (int q = 0; q < 4; q++) acc[i][j][q] = 0.f;

        for (int kt = 0; kt < KT; kt++, ci++) {
            cp_wait1();
            __syncthreads();
            int st = ci % 3;
            const u32 asb = sbase + (u32)st*SR_AST;
            const u32 bsb = sbase + SR_BOFF + (u32)st*SR_BST;
#pragma unroll
            for (int ks = 0; ks < 2; ks++) {
                u32 af[4][4], bf[8][2];
#pragma unroll
                for (int mt = 0; mt < 4; mt++) {
                    u32 aaddr = asb + (u32)(((arow + mt*16 + a_dr)*B_STR + ks*16 + a_dk) * 2);
                    ldsm4(af[mt][0], af[mt][1], af[mt][2], af[mt][3], aaddr);
                }
#pragma unroll
                for (int p = 0; p < 4; p++) {
                    u32 baddr = bsb + (u32)(((bcol + p*16 + b_dc)*B_STR + ks*16 + b_dk) * 2);
                    ldsm4(bf[2*p][0], bf[2*p][1], bf[2*p+1][0], bf[2*p+1][1], baddr);
                }
#pragma unroll
                for (int mt = 0; mt < 4; mt++)
#pragma unroll
                    for (int nt = 0; nt < 8; nt++)
                        mma_bf16(acc[mt][nt], af[mt], bf[nt]);
            }
            if (ci + 2 < TOT) fillC(ci + 2);
            else cp_commit();
        }

        const int ncol0 = ny * 128;
#pragma unroll
        for (int nt = 0; nt < 8; nt++) {
            int cl = bcol + nt*8 + 2*tig;
            int colG = ncol0 + cl;
            float b0 = bias[colG], b1 = bias[colG + 1];
            float g0 = gate[b*256 + colG], g1 = gate[b*256 + colG + 1];
#pragma unroll
            for (int mt = 0; mt < 4; mt++) {
                int r0 = arow + mt*16 + g;
                int r1 = r0 + 8;
                size_t gr0 = (size_t)m0 + r0, gr1 = (size_t)m0 + r1;
                float2 q0 = *(const float2*)(R + gr0*256 + colG);
                float2 q1 = *(const float2*)(R + gr1*256 + colG);
                sbuf[r0*129 + cl]     = acc[mt][nt][0] + b0 + q0.x*g0;
                sbuf[r0*129 + cl + 1] = acc[mt][nt][1] + b1 + q0.y*g1;
                sbuf[r1*129 + cl]     = acc[mt][nt][2] + b0 + q1.x*g0;
                sbuf[r1*129 + cl + 1] = acc[mt][nt][3] + b1 + q1.y*g1;
            }
        }
        __syncthreads();
        const int vj = lane & 7, vw = lane >> 3;
        for (int it = wid; it < 1024; it += 8) {
            int c = it >> 3, i = it & 7;
            float v = sbuf[(vw*64 + i*8 + vj)*129 + c];
            out[((size_t)(b*256 + ncol0 + c)*HH + hw8 + i)*WW_ + w0g + lane] = v;
        }
        __syncthreads();
    }
}

// -------------------- SE gate from completed pooled sums --------------------
__global__ void __launch_bounds__(256) k_pool_gate(const float* __restrict__ part,
                                                   const float* __restrict__ w1,
                                                   const float* __restrict__ b1,
                                                   const float* __restrict__ w2,
                                                   const float* __restrict__ b2,
                                                   float* __restrict__ gate) {
    int b = blockIdx.x;
    float pooled = part[b*256 + threadIdx.x] * (1.f / (float)TOK_PER_B);
    __shared__ float sp[256];
    __shared__ float hid[16];
    sp[threadIdx.x] = pooled;
    __syncthreads();
    if (threadIdx.x < 16) {
        float a = b1[threadIdx.x];
        for (int c = 0; c < 256; c++) a = fmaf(sp[c], w1[c*16 + threadIdx.x], a);
        hid[threadIdx.x] = fmaxf(a, 0.f);
    }
    __syncthreads();
    float g = b2[threadIdx.x];
#pragma unroll
    for (int j = 0; j < 16; j++) g = fmaf(hid[j], w2[j*256 + threadIdx.x], g);
    gate[b*256 + threadIdx.x] = 1.f / (1.f + __expf(-g));
}

// ---------------------------------------------------------------------------
extern "C" void kernel_launch(void* const* d_in, const int* in_sizes, int n_in,
                              void* d_out, int out_size) {
    const float* x      = (const float*)d_in[0];
    const float* n1_g   = (const float*)d_in[1];
    const float* n1_b   = (const float*)d_in[2];
    const float* qkv_w  = (const float*)d_in[3];
    const float* qkv_b  = (const float*)d_in[4];
    const float* proj_w = (const float*)d_in[5];
    const float* proj_b = (const float*)d_in[6];
    const float* rel_b  = (const float*)d_in[7];
    const float* se_w1  = (const float*)d_in[8];
    const float* se_b1  = (const float*)d_in[9];
    const float* se_w2  = (const float*)d_in[10];
    const float* se_b2  = (const float*)d_in[11];
    const float* n3_g   = (const float*)d_in[12];
    const float* n3_b   = (const float*)d_in[13];
    const float* mlp_w1 = (const float*)d_in[14];
    const float* mlp_b1 = (const float*)d_in[15];
    const float* mlp_w2 = (const float*)d_in[16];
    const float* mlp_b2 = (const float*)d_in[17];
    float* out = (float*)d_out;

    float *wins, *hbuf, *big, *part, *gate, *wb;
    cudaGetSymbolAddress((void**)&wins, g_wins);
    cudaGetSymbolAddress((void**)&hbuf, g_h);
    cudaGetSymbolAddress((void**)&big,  g_big);
    cudaGetSymbolAddress((void**)&part, g_part);
    cudaGetSymbolAddress((void**)&gate, g_gate);
    cudaGetSymbolAddress((void**)&wb,   g_wb);

    __nv_bfloat16* wbf   = (__nv_bfloat16*)wb;
    __nv_bfloat16* qkvW  = wbf;            // packed [8][96][256]
    __nv_bfloat16* projW = wbf + 196608;   // [256,256]
    __nv_bfloat16* w1W   = wbf + 262144;   // [1024,256]
    __nv_bfloat16* w2W   = wbf + 524288;   // [256,1024]
    __nv_bfloat16* bigb  = (__nv_bfloat16*)big;
    __nv_bfloat16* hb    = (__nv_bfloat16*)hbuf;

    cudaFuncSetAttribute(k_fused_qkv_attn, cudaFuncAttributeMaxDynamicSharedMemorySize, FS_SMEM);
    cudaFuncSetAttribute(k_gemm_smA,    cudaFuncAttributeMaxDynamicSharedMemorySize, SMA_SMEM);
    cudaFuncSetAttribute(k_gemm_sA_rev, cudaFuncAttributeMaxDynamicSharedMemorySize, SR_SMEM);

    dim3 b328(32, 8);
    dim3 gtr(WW_/32, HH, BATCH*8);

    k_winpart<<<gtr, b328>>>(x, wins, part);                              // 1
    k_wprep2<<<448, b328>>>(qkv_w, qkvW, 256, 768, 192, 1,                // 2 (qkv packed + w1)
                            mlp_w1, w1W, 256, 1024);
    k_wprep2<<<320, b328>>>(proj_w, projW, 256, 256, 64, 0,               // 3 (proj + w2)
                            mlp_w2, w2W, 1024, 256);
    k_fused_qkv_attn<<<NTOK/256, 256, FS_SMEM>>>(wins, n1_g, n1_b,        // 4 <- profiled
                                                 qkvW, qkv_b, rel_b, hb);
    k_gemm_smA<<<NTOK/256, 256, SMA_SMEM>>>(hb, 1, nullptr, nullptr, nullptr,
                                            projW, proj_b, wins,
                                            wins, 0, 0, 256, part);
    k_pool_gate<<<BATCH, 256>>>(part, se_w1, se_b1, se_w2, se_b2, gate);
    k_gemm_smA<<<NTOK/256, 256, SMA_SMEM>>>(wins, 0, n3_g, n3_b, gate,
                                            w1W, mlp_b1, nullptr,
                                            bigb, 1, 1, 1024, nullptr);
    k_gemm_sA_rev<<<NTOK/256, 256, SR_SMEM>>>(bigb, w2W, mlp_b2, wins, gate, out);
}

// round 15
// speedup vs baseline: 1.1157x; 1.0202x over previous
#include <cuda_runtime.h>
#include <cuda_bf16.h>
#include <cstdint>
#include <math.h>

// ---------------------------------------------------------------------------
// HATBlock — Round 15: fused QKV+attention at 128-token tiles, 2 CTAs/SM.
// B=4, C=256, H=W=192, WS=8, NH=8, HD=32
// ---------------------------------------------------------------------------

#define BATCH 4
#define DIM   256
#define HH    192
#define WW_   192
#define NWH   24
#define NWIN  (BATCH*NWH*NWH)   // 2304
#define NTOK  (NWIN*64)         // 147456
#define NH    8
#define TOK_PER_B (HH*WW_)      // 36864

typedef unsigned long long u64;
typedef unsigned int u32;

// -------------------- scratch (device globals; no runtime alloc) -----------
__device__ float g_wins[(size_t)NTOK*256];
__device__ float g_h   [(size_t)NTOK*256];
__device__ float g_big [(size_t)NTOK*512];
__device__ float g_part[1024];
__device__ float g_gate[BATCH*256];
__device__ float g_wb  [786432/2];

__device__ __forceinline__ float gelu_exact(float x) {
    return 0.5f * x * (1.0f + erff(x * 0.70710678118654752f));
}

__device__ __forceinline__ void cp_async16(void* smem, const void* gmem) {
    unsigned s = (unsigned)__cvta_generic_to_shared(smem);
    asm volatile("cp.async.ca.shared.global [%0], [%1], 16;" :: "r"(s), "l"(gmem));
}
__device__ __forceinline__ void cp_commit() { asm volatile("cp.async.commit_group;"); }
__device__ __forceinline__ void cp_wait0()  { asm volatile("cp.async.wait_group 0;" ::: "memory"); }
__device__ __forceinline__ void cp_wait1()  { asm volatile("cp.async.wait_group 1;" ::: "memory"); }
__device__ __forceinline__ void cp_wait2()  { asm volatile("cp.async.wait_group 2;" ::: "memory"); }

__device__ __forceinline__ void mma_bf16(float* c, const u32* a, const u32* b) {
    asm volatile(
        "mma.sync.aligned.m16n8k16.row.col.f32.bf16.bf16.f32 "
        "{%0,%1,%2,%3},{%4,%5,%6,%7},{%8,%9},{%0,%1,%2,%3};"
        : "+f"(c[0]), "+f"(c[1]), "+f"(c[2]), "+f"(c[3])
        : "r"(a[0]), "r"(a[1]), "r"(a[2]), "r"(a[3]), "r"(b[0]), "r"(b[1]));
}

__device__ __forceinline__ void ldsm4(u32& r0, u32& r1, u32& r2, u32& r3, u32 addr) {
    asm volatile("ldmatrix.sync.aligned.m8n8.x4.shared.b16 {%0,%1,%2,%3}, [%4];"
                 : "=r"(r0), "=r"(r1), "=r"(r2), "=r"(r3) : "r"(addr));
}

__device__ __forceinline__ u32 packbf(float a, float b) {
    __nv_bfloat162 t = __float22bfloat162_rn(make_float2(a, b));
    return *(u32*)&t;
}

// -------------------- weight prep: fp32 [K,N] -> bf16 [N,K] (+row remap) ---
__device__ __forceinline__ void wprep_body(const float* in, __nv_bfloat16* out,
                                           int K, int N, int n0, int k0, int outRow0) {
    __shared__ float tile[32][33];
    for (int r = threadIdx.y; r < 32; r += 8)
        tile[r][threadIdx.x] = in[(size_t)(k0 + r) * N + n0 + threadIdx.x];
    __syncthreads();
    for (int r = threadIdx.y; r < 32; r += 8)
        out[(size_t)(outRow0 + r) * K + k0 + threadIdx.x] = __float2bfloat16_rn(tile[threadIdx.x][r]);
}

__global__ void k_wprep2(const float* __restrict__ inA, __nv_bfloat16* __restrict__ outA,
                         int KA, int NA, int nblkA, int remapA,
                         const float* __restrict__ inB, __nv_bfloat16* __restrict__ outB,
                         int KB, int NB) {
    int blk = blockIdx.x;
    if (blk < nblkA) {
        int w = NA / 32;
        int n0 = (blk % w) * 32, k0 = (blk / w) * 32;
        int outRow0 = n0;
        if (remapA) {
            int part = n0 >> 8, h = (n0 & 255) >> 5;
            outRow0 = h * 96 + part * 32;
        }
        wprep_body(inA, outA, KA, NA, n0, k0, outRow0);
    } else {
        blk -= nblkA;
        int w = NB / 32;
        int n0 = (blk % w) * 32, k0 = (blk / w) * 32;
        wprep_body(inB, outB, KB, NB, n0, k0, n0);
    }
}

// -------------------- window partition (+ zero pooled sums) ----------------
__global__ void k_winpart(const float* __restrict__ x, float* __restrict__ wins,
                          float* __restrict__ part) {
    int w0 = blockIdx.x * 32, hh = blockIdx.y;
    int b = blockIdx.z >> 3, c0 = (blockIdx.z & 7) * 32;
    if (blockIdx.x == 0 && blockIdx.y == 0 && blockIdx.z == 0) {
        int t = threadIdx.y * 32 + threadIdx.x;
#pragma unroll
        for (int i = 0; i < 4; i++) part[t + 256*i] = 0.f;
    }
    __shared__ float tile[32][33];
    for (int cc = threadIdx.y; cc < 32; cc += 8)
        tile[cc][threadIdx.x] =
            x[(((size_t)b*256 + c0 + cc)*HH + hh)*WW_ + w0 + threadIdx.x];
    __syncthreads();
    int hw = hh >> 3, i = hh & 7;
    for (int wi = threadIdx.y; wi < 32; wi += 8) {
        int w = w0 + wi, ww = w >> 3, j = w & 7;
        size_t t = (((size_t)b*NWH + hw)*NWH + ww)*64 + i*8 + j;
        wins[t*256 + c0 + threadIdx.x] = tile[threadIdx.x][wi];
    }
}

// ============================================================================
// Fused QKV GEMM + window attention.  CTA = 128 tokens (2 windows), 8 warps,
// 2 CTAs/SM.  Per head: GEMM 128x96x256 (warps 4m x 2n, warp 32x48, K chunk
// 32, 2-stage W ring) -> Q,K tile + V transposed tile; then warp =
// (window, quarter) attention 16 q-rows x 64 keys; O -> hb bf16.
// smem: Ab 128x264 @0; QK 128x72 @67,584; Vt 32x136 @86,016;
//       ring 2x7,680 @94,720; pb 96f @110,080; sbt 225f @110,464.
// ============================================================================
#define F_AB_STR 264
#define F_QK_STR 72
#define F_VT_STR 136
#define FS_QK   67584
#define FS_VT   86016
#define FS_RING 94720
#define FS_RSTG 7680
#define FS_PB   110080
#define FS_SB   110464
#define FS_SMEM 111368

__global__ void __launch_bounds__(256, 2)
k_fused_qkv_attn(const float* __restrict__ Ain,
                 const float* __restrict__ lng, const float* __restrict__ lnb,
                 const __nv_bfloat16* __restrict__ Wt,   // packed [8][96][256]
                 const float* __restrict__ qkv_b,
                 const float* __restrict__ rel_bias,
                 __nv_bfloat16* __restrict__ hb)
{
    extern __shared__ char smem[];
    __nv_bfloat16* Ab  = (__nv_bfloat16*)smem;
    __nv_bfloat16* qk  = (__nv_bfloat16*)(smem + FS_QK);
    __nv_bfloat16* vT  = (__nv_bfloat16*)(smem + FS_VT);
    float* pb  = (float*)(smem + FS_PB);
    float* sbt = (float*)(smem + FS_SB);
    const u32 sbase = (u32)__cvta_generic_to_shared(smem);

    const int tid = threadIdx.x, lane = tid & 31, wid = tid >> 5;
    const int g = lane >> 2, tig = lane & 3;
    const int m0 = blockIdx.x * 128;

    const int a_dr = (lane & 7) | (((lane >> 3) & 1) << 3);
    const int a_dk = (lane >> 4) << 3;
    const int quad = lane >> 3;
    const int b_dc = (lane & 7) + ((quad & 2) ? 8 : 0);
    const int b_dk = (quad & 1) << 3;

    const int wm = wid & 3;      // GEMM m-warp (32 rows)
    const int wn = wid >> 2;     // GEMM n-warp (48 cols)
    const int wi = wid >> 2;     // attention window (0,1)
    const int qt = wid & 3;      // attention quarter (16 rows)

    // W chunk filler: hc = h*8 + ck; 96 rows x 32 K, stride 40
    auto fillW = [&](int hc) {
        __nv_bfloat16* Bs = (__nv_bfloat16*)(smem + FS_RING + (hc & 1) * FS_RSTG);
        const __nv_bfloat16* Wg = Wt + (size_t)(hc >> 3) * 96 * 256 + (hc & 7) * 32;
#pragma unroll
        for (int i = 0; i < 2; i++) {
            int idx = tid + 256*i;          // 0..511, need 384
            if (idx < 384) {
                int row = idx >> 2, seg = idx & 3;
                cp_async16(Bs + row*40 + seg*8, Wg + (size_t)row*256 + seg*8);
            }
        }
        cp_commit();
    };
    fillW(0); fillW(1);

    // ---- fused LN of A tile (fp32 gmem -> bf16 smem) ----
    {
        const float* Ag = Ain + (size_t)m0 * 256;
        float lg[8], lb[8];
#pragma unroll
        for (int j = 0; j < 8; j++) {
            int c = lane*8 + j;
            lg[j] = lng[c]; lb[j] = lnb[c];
        }
#pragma unroll 1
        for (int i = 0; i < 16; i++) {
            int r = wid*16 + i;
            const float4* rp = (const float4*)(Ag + (size_t)r * 256 + lane*8);
            float4 va = rp[0], vb = rp[1];
            float v[8] = {va.x, va.y, va.z, va.w, vb.x, vb.y, vb.z, vb.w};
            float s = 0.f, s2 = 0.f;
#pragma unroll
            for (int j = 0; j < 8; j++) { s += v[j]; s2 += v[j]*v[j]; }
#pragma unroll
            for (int o = 16; o; o >>= 1) {
                s  += __shfl_xor_sync(0xffffffffu, s,  o);
                s2 += __shfl_xor_sync(0xffffffffu, s2, o);
            }
            float mean = s * (1.f/256.f);
            float var  = s2 * (1.f/256.f) - mean*mean;
            float inv  = rsqrtf(var + 1e-5f);
#pragma unroll
            for (int k = 0; k < 4; k++) {
                float n0 = (v[2*k  ]-mean)*inv*lg[2*k  ] + lb[2*k  ];
                float n1 = (v[2*k+1]-mean)*inv*lg[2*k+1] + lb[2*k+1];
                *(u32*)&Ab[r*F_AB_STR + lane*8 + 2*k] = packbf(n0, n1);
            }
        }
    }

#pragma unroll 1
    for (int h = 0; h < 8; h++) {
        // ---- GEMM 128x96x256 for this head ----
        float acc[2][6][4];
#pragma unroll
        for (int i = 0; i < 2; i++)
#pragma unroll
            for (int j = 0; j < 6; j++)
#pragma unroll
                for (int q = 0; q < 4; q++) acc[i][j][q] = 0.f;

#pragma unroll 1
        for (int ck = 0; ck < 8; ck++) {
            const int hc = h*8 + ck;
            if (hc == 63) cp_wait0(); else cp_wait1();
            __syncthreads();
            if (ck == 0) {
                // per-head bias + rel-bias tables (visible by epilogue via chunk syncs)
                for (int j = tid; j < 96; j += 256)
                    pb[j] = qkv_b[(j >> 5)*256 + h*32 + (j & 31)];
                for (int rr = tid; rr < 225; rr += 256)
                    sbt[rr] = rel_bias[rr*NH + h];
            }
            const u32 rb = sbase + FS_RING + (u32)(hc & 1) * FS_RSTG;
#pragma unroll
            for (int ks = 0; ks < 2; ks++) {
                const int kb = ck*32 + ks*16;
                u32 af[2][4], bf[6][2];
#pragma unroll
                for (int mt = 0; mt < 2; mt++) {
                    u32 aaddr = sbase + (u32)(((wm*32 + mt*16 + a_dr)*F_AB_STR + kb + a_dk) * 2);
                    ldsm4(af[mt][0], af[mt][1], af[mt][2], af[mt][3], aaddr);
                }
#pragma unroll
                for (int p = 0; p < 3; p++) {
                    u32 baddr = rb + (u32)(((wn*48 + p*16 + b_dc)*40 + ks*16 + b_dk) * 2);
                    ldsm4(bf[2*p][0], bf[2*p][1], bf[2*p+1][0], bf[2*p+1][1], baddr);
                }
#pragma unroll
                for (int mt = 0; mt < 2; mt++)
#pragma unroll
                    for (int nt = 0; nt < 6; nt++)
                        mma_bf16(acc[mt][nt], af[mt], bf[nt]);
            }
            __syncthreads();
            if (hc + 2 < 64) fillW(hc + 2);
        }

        // ---- epilogue: Q,K -> qk tile; V -> transposed vT tile ----
#pragma unroll
        for (int nt = 0; nt < 6; nt++) {
            int colj = wn*48 + nt*8 + 2*tig;     // 0..95
            float b0 = pb[colj], b1 = pb[colj + 1];
#pragma unroll
            for (int mt = 0; mt < 2; mt++) {
                int r0 = wm*32 + mt*16 + g, r1 = r0 + 8;
                float v00 = acc[mt][nt][0] + b0, v01 = acc[mt][nt][1] + b1;
                float v10 = acc[mt][nt][2] + b0, v11 = acc[mt][nt][3] + b1;
                if (colj < 64) {
                    *(u32*)&qk[r0*F_QK_STR + colj] = packbf(v00, v01);
                    *(u32*)&qk[r1*F_QK_STR + colj] = packbf(v10, v11);
                } else {
                    int c = colj - 64;
                    vT[c*F_VT_STR + r0]     = __float2bfloat16_rn(v00);
                    vT[(c+1)*F_VT_STR + r0] = __float2bfloat16_rn(v01);
                    vT[c*F_VT_STR + r1]     = __float2bfloat16_rn(v10);
                    vT[(c+1)*F_VT_STR + r1] = __float2bfloat16_rn(v11);
                }
            }
        }
        __syncthreads();

        // ---- attention: warp = (window wi, quarter qt): 16 q-rows x 64 keys
        u32 aQ[2][4];
#pragma unroll
        for (int ks = 0; ks < 2; ks++) {
            u32 aaddr = sbase + FS_QK +
                (u32)(((wi*64 + qt*16 + a_dr)*F_QK_STR + ks*16 + a_dk) * 2);
            ldsm4(aQ[ks][0], aQ[ks][1], aQ[ks][2], aQ[ks][3], aaddr);
        }

        float S[8][4];
#pragma unroll
        for (int j = 0; j < 8; j++)
#pragma unroll
            for (int q = 0; q < 4; q++) S[j][q] = 0.f;

#pragma unroll
        for (int ks = 0; ks < 2; ks++) {
            u32 bK[8][2];
#pragma unroll
            for (int p = 0; p < 4; p++) {
                u32 baddr = sbase + FS_QK +
                    (u32)(((wi*64 + p*16 + b_dc)*F_QK_STR + 32 + ks*16 + b_dk) * 2);
                ldsm4(bK[2*p][0], bK[2*p][1], bK[2*p+1][0], bK[2*p+1][1], baddr);
            }
#pragma unroll
            for (int nt = 0; nt < 8; nt++)
                mma_bf16(S[nt], aQ[ks], bK[nt]);
        }

        // scale + relative bias
#pragma unroll
        for (int nt = 0; nt < 8; nt++)
#pragma unroll
            for (int rr = 0; rr < 2; rr++)
#pragma unroll
                for (int e = 0; e < 2; e++) {
                    int di = qt*2 + rr - nt + 7;
                    int dj = g - (2*tig + e) + 7;
                    S[nt][rr*2+e] = S[nt][rr*2+e] * 0.17677669529663687f
                                  + sbt[di*15 + dj];
                }

        // softmax
        float lrow[2];
#pragma unroll
        for (int rr = 0; rr < 2; rr++) {
            float mx = -1e30f;
#pragma unroll
            for (int nt = 0; nt < 8; nt++) {
                mx = fmaxf(mx, S[nt][rr*2]);
                mx = fmaxf(mx, S[nt][rr*2+1]);
            }
            mx = fmaxf(mx, __shfl_xor_sync(0xffffffffu, mx, 1));
            mx = fmaxf(mx, __shfl_xor_sync(0xffffffffu, mx, 2));
            float sum = 0.f;
#pragma unroll
            for (int nt = 0; nt < 8; nt++) {
                float p0 = __expf(S[nt][rr*2]   - mx);
                float p1 = __expf(S[nt][rr*2+1] - mx);
                S[nt][rr*2] = p0; S[nt][rr*2+1] = p1;
                sum += p0 + p1;
            }
            sum += __shfl_xor_sync(0xffffffffu, sum, 1);
            sum += __shfl_xor_sync(0xffffffffu, sum, 2);
            lrow[rr] = sum;
        }

        // O = P V
        float O[4][4];
#pragma unroll
        for (int j = 0; j < 4; j++)
#pragma unroll
            for (int q = 0; q < 4; q++) O[j][q] = 0.f;
#pragma unroll
        for (int ks2 = 0; ks2 < 4; ks2++) {
            u32 bV[4][2];
#pragma unroll
            for (int p = 0; p < 2; p++) {
                u32 vaddr = sbase + FS_VT +
                    (u32)(((p*16 + b_dc)*F_VT_STR + wi*64 + ks2*16 + b_dk) * 2);
                ldsm4(bV[2*p][0], bV[2*p][1], bV[2*p+1][0], bV[2*p+1][1], vaddr);
            }
            u32 pa[4];
            pa[0] = packbf(S[2*ks2  ][0], S[2*ks2  ][1]);
            pa[1] = packbf(S[2*ks2  ][2], S[2*ks2  ][3]);
            pa[2] = packbf(S[2*ks2+1][0], S[2*ks2+1][1]);
            pa[3] = packbf(S[2*ks2+1][2], S[2*ks2+1][3]);
#pragma unroll
            for (int nt2 = 0; nt2 < 4; nt2++)
                mma_bf16(O[nt2], pa, bV[nt2]);
        }

        // normalize + store
        float inv0 = 1.f / lrow[0], inv1 = 1.f / lrow[1];
        size_t rg = (size_t)m0 + wi*64 + qt*16 + g;
#pragma unroll
        for (int nt2 = 0; nt2 < 4; nt2++) {
            __nv_bfloat16* p0 = hb + rg*256 + h*32 + nt2*8 + 2*tig;
            *(u32*)(p0)         = packbf(O[nt2][0]*inv0, O[nt2][1]*inv0);
            *(u32*)(p0 + 8*256) = packbf(O[nt2][2]*inv1, O[nt2][3]*inv1);
        }
    }
}

// ============================================================================
// GEMM 1 (proj / MLP1): CTA 256x128, 8 warps, warp 64x64, K chunk 32.
// ============================================================================
#define AB_STR 264
#define B_STR  40
#define SMA_BR   135168
#define SMA_SCOL 176128
#define SMA_SMEM 176640

__global__ void __launch_bounds__(256, 1)
k_gemm_smA(const void* __restrict__ Ain, int a_bf16,
           const float* __restrict__ lng, const float* __restrict__ lnb,
           const float* __restrict__ gate,
           const __nv_bfloat16* __restrict__ Wt,
           const float* __restrict__ bias,
           const float* __restrict__ R,
           void* __restrict__ Cout, int c_bf16, int act,
           int Nfull, float* __restrict__ pool)
{
    extern __shared__ char smem[];
    __nv_bfloat16* Ab = (__nv_bfloat16*)smem;
    char*  Bring = smem + SMA_BR;
    float* scol = (float*)(smem + SMA_SCOL);
    const u32 sbase = (u32)__cvta_generic_to_shared(smem);

    const int tid = threadIdx.x, lane = tid & 31, wid = tid >> 5;
    const int g = lane >> 2, tig = lane & 3;
    const int arow = (wid & 3) * 64;
    const int bcol = (wid >> 2) * 64;
    const int m0 = blockIdx.x * 256;
    const int b  = m0 / TOK_PER_B;

    const int a_dr = (lane & 7) | (((lane >> 3) & 1) << 3);
    const int a_dk = (lane >> 4) << 3;
    const int quad = lane >> 3;
    const int b_dc = (lane & 7) + ((quad & 2) ? 8 : 0);
    const int b_dk = (quad & 1) << 3;

    if (a_bf16) {
        const __nv_bfloat16* Ag = (const __nv_bfloat16*)Ain + (size_t)m0 * 256;
#pragma unroll
        for (int i = 0; i < 32; i++) {
            int idx = tid + 256*i;
            int r = idx >> 5, c8 = idx & 31;
            cp_async16(Ab + r*AB_STR + c8*8, Ag + (size_t)r*256 + c8*8);
        }
        cp_commit();
    } else {
        const float* Ag = (const float*)Ain + (size_t)m0 * 256;
        const float* gp = gate ? (gate + b*256) : nullptr;
        float gv[8], lg[8], lb[8];
#pragma unroll
        for (int j = 0; j < 8; j++) {
            int c = lane*8 + j;
            gv[j] = gp ? gp[c] : 1.f;
            lg[j] = lng[c]; lb[j] = lnb[c];
        }
#pragma unroll 1
        for (int i = 0; i < 32; i++) {
            int r = wid*32 + i;
            const float4* rp = (const float4*)(Ag + (size_t)r * 256 + lane*8);
            float4 va = rp[0], vb = rp[1];
            float v[8] = {va.x, va.y, va.z, va.w, vb.x, vb.y, vb.z, vb.w};
            float s = 0.f, s2 = 0.f;
#pragma unroll
            for (int j = 0; j < 8; j++) {
                v[j] *= gv[j]; s += v[j]; s2 += v[j]*v[j];
            }
#pragma unroll
            for (int o = 16; o; o >>= 1) {
                s  += __shfl_xor_sync(0xffffffffu, s,  o);
                s2 += __shfl_xor_sync(0xffffffffu, s2, o);
            }
            float mean = s * (1.f/256.f);
            float var  = s2 * (1.f/256.f) - mean*mean;
            float inv  = rsqrtf(var + 1e-5f);
#pragma unroll
            for (int k = 0; k < 4; k++) {
                float n0 = (v[2*k  ]-mean)*inv*lg[2*k  ] + lb[2*k  ];
                float n1 = (v[2*k+1]-mean)*inv*lg[2*k+1] + lb[2*k+1];
                *(u32*)&Ab[r*AB_STR + lane*8 + 2*k] = packbf(n0, n1);
            }
        }
        __syncthreads();
    }

    const int NY = Nfull >> 7;
    const int KT = 8;
    const int TOT = NY * KT;

    auto fillB = [&](int c) {
        int ny2 = c >> 3, kt2 = c & 7, st = c & 3;
        __nv_bfloat16* Bs = (__nv_bfloat16*)(Bring + st*10240);
        const __nv_bfloat16* Wg = Wt + (size_t)(ny2*128) * 256 + kt2*32;
#pragma unroll
        for (int i = 0; i < 2; i++) {
            int idx = tid + 256*i;
            int row = idx >> 2, seg = idx & 3;
            cp_async16(Bs + row*B_STR + seg*8, Wg + (size_t)row*256 + seg*8);
        }
        cp_commit();
    };
    fillB(0); fillB(1); fillB(2);

    int ci = 0;
    for (int ny = 0; ny < NY; ny++) {
        float acc[4][8][4];
#pragma unroll
        for (int i = 0; i < 4; i++)
#pragma unroll
            for (int j = 0; j < 8; j++)
#pragma unroll
                for (int q = 0; q < 4; q++) acc[i][j][q] = 0.f;

        for (int kt = 0; kt < KT; kt++, ci++) {
            cp_wait2();
            __syncthreads();
            const u32 bsb = sbase + SMA_BR + (u32)(ci & 3)*10240;
#pragma unroll
            for (int ks = 0; ks < 2; ks++) {
                const int kb = kt*32 + ks*16;
                u32 af[4][4], bf[8][2];
#pragma unroll
                for (int mt = 0; mt < 4; mt++) {
                    u32 aaddr = sbase + (u32)(((arow + mt*16 + a_dr)*AB_STR + kb + a_dk) * 2);
                    ldsm4(af[mt][0], af[mt][1], af[mt][2], af[mt][3], aaddr);
                }
#pragma unroll
                for (int p = 0; p < 4; p++) {
                    u32 baddr = bsb + (u32)(((bcol + p*16 + b_dc)*B_STR + ks*16 + b_dk) * 2);
                    ldsm4(bf[2*p][0], bf[2*p][1], bf[2*p+1][0], bf[2*p+1][1], baddr);
                }
#pragma unroll
                for (int mt = 0; mt < 4; mt++)
#pragma unroll
                    for (int nt = 0; nt < 8; nt++)
                        mma_bf16(acc[mt][nt], af[mt], bf[nt]);
            }
            if (ci + 3 < TOT) fillB(ci + 3);
            else cp_commit();
        }

        const int ncol0 = ny * 128;
        if (c_bf16) {
            __nv_bfloat16* Cb = (__nv_bfloat16*)Cout;
#pragma unroll
            for (int nt = 0; nt < 8; nt++) {
                int colG = ncol0 + bcol + nt*8 + 2*tig;
                float b0 = bias[colG], b1 = bias[colG + 1];
#pragma unroll
                for (int mt = 0; mt < 4; mt++) {
                    size_t r0 = (size_t)m0 + arow + mt*16 + g;
                    size_t r1 = r0 + 8;
                    float v00 = acc[mt][nt][0] + b0, v01 = acc[mt][nt][1] + b1;
                    float v10 = acc[mt][nt][2] + b0, v11 = acc[mt][nt][3] + b1;
                    if (act) {
                        v00 = gelu_exact(v00); v01 = gelu_exact(v01);
                        v10 = gelu_exact(v10); v11 = gelu_exact(v11);
                    }
                    *(u32*)((__nv_bfloat16*)Cb + r0*Nfull + colG) = packbf(v00, v01);
                    *(u32*)((__nv_bfloat16*)Cb + r1*Nfull + colG) = packbf(v10, v11);
                }
            }
        } else {
            float* Cf = (float*)Cout;
            float psum[8][2];
#pragma unroll
            for (int nt = 0; nt < 8; nt++) { psum[nt][0] = 0.f; psum[nt][1] = 0.f; }
#pragma unroll
            for (int nt = 0; nt < 8; nt++) {
                int colG = ncol0 + bcol + nt*8 + 2*tig;
                float b0 = bias[colG], b1 = bias[colG + 1];
#pragma unroll
                for (int mt = 0; mt < 4; mt++) {
                    size_t r0 = (size_t)m0 + arow + mt*16 + g;
                    size_t r1 = r0 + 8;
                    float2 q0 = *(const float2*)(R + r0*Nfull + colG);
                    float2 q1 = *(const float2*)(R + r1*Nfull + colG);
                    float v00 = acc[mt][nt][0] + b0 + q0.x, v01 = acc[mt][nt][1] + b1 + q0.y;
                    float v10 = acc[mt][nt][2] + b0 + q1.x, v11 = acc[mt][nt][3] + b1 + q1.y;
                    *(float2*)(Cf + r0*Nfull + colG) = make_float2(v00, v01);
                    *(float2*)(Cf + r1*Nfull + colG) = make_float2(v10, v11);
                    psum[nt][0] += v00 + v10; psum[nt][1] += v01 + v11;
                }
            }
            if (pool) {
                __syncthreads();
                if (tid < 128) scol[tid] = 0.f;
                __syncthreads();
#pragma unroll
                for (int nt = 0; nt < 8; nt++) {
                    int colL = bcol + nt*8 + 2*tig;
                    atomicAdd(&scol[colL],     psum[nt][0]);
                    atomicAdd(&scol[colL + 1], psum[nt][1]);
                }
                __syncthreads();
                if (tid < 128) atomicAdd(pool + b*256 + ncol0 + tid, scol[tid]);
                __syncthreads();
            }
        }
    }
}

// ============================================================================
// GEMM 2 (MLP2) + fused window-reverse (256 tokens = 4 windows per CTA).
// ============================================================================
#define SR_AST 20480
#define SR_BOFF 61440
#define SR_BST 10240
#define SR_STAGE 92160
#define SR_SMEM 224256
__global__ void __launch_bounds__(256, 1)
k_gemm_sA_rev(const __nv_bfloat16* __restrict__ Ain,
              const __nv_bfloat16* __restrict__ Wt,
              const float* __restrict__ bias,
              const float* __restrict__ R,
              const float* __restrict__ gate,
              float* __restrict__ out)
{
    extern __shared__ char smem[];
    const u32 sbase = (u32)__cvta_generic_to_shared(smem);
    float* sbuf = (float*)(smem + SR_STAGE);

    const int tid = threadIdx.x, lane = tid & 31, wid = tid >> 5;
    const int g = lane >> 2, tig = lane & 3;
    const int arow = (wid & 3) * 64;
    const int bcol = (wid >> 2) * 64;
    const int m0 = blockIdx.x * 256;
    const int b  = m0 / TOK_PER_B;

    const int win0 = m0 >> 6;
    const int rem  = win0 - b * (NWH*NWH);
    const int hw8  = (rem / NWH) * 8;
    const int w0g  = (rem % NWH) * 8;

    const int a_dr = (lane & 7) | (((lane >> 3) & 1) << 3);
    const int a_dk = (lane >> 4) << 3;
    const int quad = lane >> 3;
    const int b_dc = (lane & 7) + ((quad & 2) ? 8 : 0);
    const int b_dk = (quad & 1) << 3;

    const int KT = 32, NY = 2, TOT = 64;
    const __nv_bfloat16* Ag = Ain + (size_t)m0 * 1024;

    auto fillC = [&](int c) {
        int ny2 = c >> 5, kt2 = c & 31, st = c % 3;
        __nv_bfloat16* As = (__nv_bfloat16*)(smem + st*SR_AST);
        __nv_bfloat16* Bs = (__nv_bfloat16*)(smem + SR_BOFF + st*SR_BST);
        const __nv_bfloat16* Wg = Wt + (size_t)(ny2*128) * 1024 + kt2*32;
        const __nv_bfloat16* Ac = Ag + kt2*32;
#pragma unroll
        for (int i = 0; i < 4; i++) {
            int idx = tid + 256*i;
            int row = idx >> 2, seg = idx & 3;
            cp_async16(As + row*B_STR + seg*8, Ac + (size_t)row*1024 + seg*8);
        }
#pragma unroll
        for (int i = 0; i < 2; i++) {
            int idx = tid + 256*i;
            int row = idx >> 2, seg = idx & 3;
            cp_async16(Bs + row*B_STR + seg*8, Wg + (size_t)row*1024 + seg*8);
        }
        cp_commit();
    };
    fillC(0); fillC(1);

    int ci = 0;
    for (int ny = 0; ny < NY; ny++) {
        float acc[4][8][4];
#pragma unroll
        for (int i = 0; i < 4; i++)
#pragma unroll
            for (int j = 0; j < 8; j++)
#pragma unroll
                for (int q = 0; q < 4; q++) acc[i][j][q] = 0.f;

        for (int kt = 0; kt < KT; kt++, ci++) {
            cp_wait1();
            __syncthreads();
            int st = ci % 3;
            const u32 asb = sbase + (u32)st*SR_AST;
            const u32 bsb = sbase + SR_BOFF + (u32)st*SR_BST;
#pragma unroll
            for (int ks = 0; ks < 2; ks++) {
                u32 af[4][4], bf[8][2];
#pragma unroll
                for (int mt = 0; mt < 4; mt++) {
                    u32 aaddr = asb + (u32)(((arow + mt*16 + a_dr)*B_STR + ks*16 + a_dk) * 2);
                    ldsm4(af[mt][0], af[mt][1], af[mt][2], af[mt][3], aaddr);
                }
#pragma unroll
                for (int p = 0; p < 4; p++) {
                    u32 baddr = bsb + (u32)(((bcol + p*16 + b_dc)*B_STR + ks*16 + b_dk) * 2);
                    ldsm4(bf[2*p][0], bf[2*p][1], bf[2*p+1][0], bf[2*p+1][1], baddr);
                }
#pragma unroll
                for (int mt = 0; mt < 4; mt++)
#pragma unroll
                    for (int nt = 0; nt < 8; nt++)
                        mma_bf16(acc[mt][nt], af[mt], bf[nt]);
            }
            if (ci + 2 < TOT) fillC(ci + 2);
            else cp_commit();
        }

        const int ncol0 = ny * 128;
#pragma unroll
        for (int nt = 0; nt < 8; nt++) {
            int cl = bcol + nt*8 + 2*tig;
            int colG = ncol0 + cl;
            float b0 = bias[colG], b1 = bias[colG + 1];
            float g0 = gate[b*256 + colG], g1 = gate[b*256 + colG + 1];
#pragma unroll
            for (int mt = 0; mt < 4; mt++) {
                int r0 = arow + mt*16 + g;
                int r1 = r0 + 8;
                size_t gr0 = (size_t)m0 + r0, gr1 = (size_t)m0 + r1;
                float2 q0 = *(const float2*)(R + gr0*256 + colG);
                float2 q1 = *(const float2*)(R + gr1*256 + colG);
                sbuf[r0*129 + cl]     = acc[mt][nt][0] + b0 + q0.x*g0;
                sbuf[r0*129 + cl + 1] = acc[mt][nt][1] + b1 + q0.y*g1;
                sbuf[r1*129 + cl]     = acc[mt][nt][2] + b0 + q1.x*g0;
                sbuf[r1*129 + cl + 1] = acc[mt][nt][3] + b1 + q1.y*g1;
            }
        }
        __syncthreads();
        const int vj = lane & 7, vw = lane >> 3;
        for (int it = wid; it < 1024; it += 8) {
            int c = it >> 3, i = it & 7;
            float v = sbuf[(vw*64 + i*8 + vj)*129 + c];
            out[((size_t)(b*256 + ncol0 + c)*HH + hw8 + i)*WW_ + w0g + lane] = v;
        }
        __syncthreads();
    }
}

// -------------------- SE gate from completed pooled sums --------------------
__global__ void __launch_bounds__(256) k_pool_gate(const float* __restrict__ part,
                                                   const float* __restrict__ w1,
                                                   const float* __restrict__ b1,
                                                   const float* __restrict__ w2,
                                                   const float* __restrict__ b2,
                                                   float* __restrict__ gate) {
    int b = blockIdx.x;
    float pooled = part[b*256 + threadIdx.x] * (1.f / (float)TOK_PER_B);
    __shared__ float sp[256];
    __shared__ float hid[16];
    sp[threadIdx.x] = pooled;
    __syncthreads();
    if (threadIdx.x < 16) {
        float a = b1[threadIdx.x];
        for (int c = 0; c < 256; c++) a = fmaf(sp[c], w1[c*16 + threadIdx.x], a);
        hid[threadIdx.x] = fmaxf(a, 0.f);
    }
    __syncthreads();
    float g = b2[threadIdx.x];
#pragma unroll
    for (int j = 0; j < 16; j++) g = fmaf(hid[j], w2[j*256 + threadIdx.x], g);
    gate[b*256 + threadIdx.x] = 1.f / (1.f + __expf(-g));
}

// ---------------------------------------------------------------------------
extern "C" void kernel_launch(void* const* d_in, const int* in_sizes, int n_in,
                              void* d_out, int out_size) {
    const float* x      = (const float*)d_in[0];
    const float* n1_g   = (const float*)d_in[1];
    const float* n1_b   = (const float*)d_in[2];
    const float* qkv_w  = (const float*)d_in[3];
    const float* qkv_b  = (const float*)d_in[4];
    const float* proj_w = (const float*)d_in[5];
    const float* proj_b = (const float*)d_in[6];
    const float* rel_b  = (const float*)d_in[7];
    const float* se_w1  = (const float*)d_in[8];
    const float* se_b1  = (const float*)d_in[9];
    const float* se_w2  = (const float*)d_in[10];
    const float* se_b2  = (const float*)d_in[11];
    const float* n3_g   = (const float*)d_in[12];
    const float* n3_b   = (const float*)d_in[13];
    const float* mlp_w1 = (const float*)d_in[14];
    const float* mlp_b1 = (const float*)d_in[15];
    const float* mlp_w2 = (const float*)d_in[16];
    const float* mlp_b2 = (const float*)d_in[17];
    float* out = (float*)d_out;

    float *wins, *hbuf, *big, *part, *gate, *wb;
    cudaGetSymbolAddress((void**)&wins, g_wins);
    cudaGetSymbolAddress((void**)&hbuf, g_h);
    cudaGetSymbolAddress((void**)&big,  g_big);
    cudaGetSymbolAddress((void**)&part, g_part);
    cudaGetSymbolAddress((void**)&gate, g_gate);
    cudaGetSymbolAddress((void**)&wb,   g_wb);

    __nv_bfloat16* wbf   = (__nv_bfloat16*)wb;
    __nv_bfloat16* qkvW  = wbf;            // packed [8][96][256]
    __nv_bfloat16* projW = wbf + 196608;   // [256,256]
    __nv_bfloat16* w1W   = wbf + 262144;   // [1024,256]
    __nv_bfloat16* w2W   = wbf + 524288;   // [256,1024]
    __nv_bfloat16* bigb  = (__nv_bfloat16*)big;
    __nv_bfloat16* hb    = (__nv_bfloat16*)hbuf;

    cudaFuncSetAttribute(k_fused_qkv_attn, cudaFuncAttributeMaxDynamicSharedMemorySize, FS_SMEM);
    cudaFuncSetAttribute(k_gemm_smA,    cudaFuncAttributeMaxDynamicSharedMemorySize, SMA_SMEM);
    cudaFuncSetAttribute(k_gemm_sA_rev, cudaFuncAttributeMaxDynamicSharedMemorySize, SR_SMEM);

    dim3 b328(32, 8);
    dim3 gtr(WW_/32, HH, BATCH*8);

    k_winpart<<<gtr, b328>>>(x, wins, part);                              // 1
    k_wprep2<<<448, b328>>>(qkv_w, qkvW, 256, 768, 192, 1,                // 2
                            mlp_w1, w1W, 256, 1024);
    k_wprep2<<<320, b328>>>(proj_w, projW, 256, 256, 64, 0,               // 3
                            mlp_w2, w2W, 1024, 256);
    k_fused_qkv_attn<<<NTOK/128, 256, FS_SMEM>>>(wins, n1_g, n1_b,        // 4 <- profiled
                                                 qkvW, qkv_b, rel_b, hb);
    k_gemm_smA<<<NTOK/256, 256, SMA_SMEM>>>(hb, 1, nullptr, nullptr, nullptr,
                                            projW, proj_b, wins,
                                            wins, 0, 0, 256, part);
    k_pool_gate<<<BATCH, 256>>>(part, se_w1, se_b1, se_w2, se_b2, gate);
    k_gemm_smA<<<NTOK/256, 256, SMA_SMEM>>>(wins, 0, n3_g, n3_b, gate,
                                            w1W, mlp_b1, nullptr,
                                            bigb, 1, 1, 1024, nullptr);
    k_gemm_sA_rev<<<NTOK/256, 256, SR_SMEM>>>(bigb, w2W, mlp_b2, wins, gate, out);
}